// round 8
// baseline (speedup 1.0000x reference)
#include <cuda_runtime.h>
#include <cuda_bf16.h>
#include <math.h>
#include <stdint.h>

#define S_LEN 4096
#define HIDDEN 2048
#define HQ 16
#define HKV 4
#define DHD 128
#define QSTR (HQ*DHD)    // 2048
#define KSTR (HKV*DHD)   // 512
#define RMS_EPS 1e-6f
#define SM_SCALE 0.08838834764831845f  // 128^-0.5

// ------------------------- scratch (static device globals) ----------------------
__device__ float g_q[S_LEN * QSTR];
__device__ float g_k[S_LEN * KSTR];
__device__ float g_v[S_LEN * KSTR];

__device__ __nv_bfloat16 g_hs_h[S_LEN * HIDDEN];
__device__ __nv_bfloat16 g_hs_l[S_LEN * HIDDEN];
__device__ __nv_bfloat16 g_at_h[S_LEN * QSTR];
__device__ __nv_bfloat16 g_at_l[S_LEN * QSTR];
__device__ __nv_bfloat16 g_qh[S_LEN * QSTR];
__device__ __nv_bfloat16 g_ql[S_LEN * QSTR];
__device__ __nv_bfloat16 g_kh[S_LEN * KSTR];
__device__ __nv_bfloat16 g_kl[S_LEN * KSTR];
__device__ __nv_bfloat16 g_vth[KSTR * S_LEN];   // [hk*128+d][s]
__device__ __nv_bfloat16 g_vtl[KSTR * S_LEN];
__device__ __nv_bfloat16 g_wq_h[QSTR * HIDDEN];
__device__ __nv_bfloat16 g_wq_l[QSTR * HIDDEN];
__device__ __nv_bfloat16 g_wk_h[KSTR * HIDDEN];
__device__ __nv_bfloat16 g_wk_l[KSTR * HIDDEN];
__device__ __nv_bfloat16 g_wv_h[KSTR * HIDDEN];
__device__ __nv_bfloat16 g_wv_l[KSTR * HIDDEN];
__device__ __nv_bfloat16 g_wo_h[HIDDEN * QSTR];
__device__ __nv_bfloat16 g_wo_l[HIDDEN * QSTR];

// ------------------------- helpers ----------------------------------------------
__device__ __forceinline__ uint32_t smem_u32(const void* p) {
    uint32_t a;
    asm("{ .reg .u64 t; cvta.to.shared.u64 t, %1; cvt.u32.u64 %0, t; }" : "=r"(a) : "l"(p));
    return a;
}
__device__ __forceinline__ void ldsm_x4(uint32_t* r, uint32_t addr) {
    asm volatile("ldmatrix.sync.aligned.m8n8.x4.shared.b16 {%0,%1,%2,%3}, [%4];"
                 : "=r"(r[0]), "=r"(r[1]), "=r"(r[2]), "=r"(r[3]) : "r"(addr));
}
__device__ __forceinline__ void mma_bf16(float* d, const uint32_t* a, const uint32_t* b,
                                         const float* c) {
    asm volatile(
        "mma.sync.aligned.m16n8k16.row.col.f32.bf16.bf16.f32 "
        "{%0,%1,%2,%3}, {%4,%5,%6,%7}, {%8,%9}, {%10,%11,%12,%13};"
        : "=f"(d[0]), "=f"(d[1]), "=f"(d[2]), "=f"(d[3])
        : "r"(a[0]), "r"(a[1]), "r"(a[2]), "r"(a[3]),
          "r"(b[0]), "r"(b[1]),
          "f"(c[0]), "f"(c[1]), "f"(c[2]), "f"(c[3]));
}
__device__ __forceinline__ void cp_async16(uint32_t dst, const void* src) {
    asm volatile("cp.async.cg.shared.global [%0], [%1], 16;" :: "r"(dst), "l"(src) : "memory");
}
__device__ __forceinline__ void cp_commit() {
    asm volatile("cp.async.commit_group;" ::: "memory");
}
template<int N> __device__ __forceinline__ void cp_wait() {
    asm volatile("cp.async.wait_group %0;" :: "n"(N) : "memory");
}
// logical tile rows of 64B (32 bf16) with XOR swizzle for conflict-free ldmatrix
__device__ __forceinline__ uint32_t swz(uint32_t tileBase, int r, int c) {
    uint32_t off = r * 64 + c * 16;
    off ^= ((off >> 7) & 7) << 4;
    return tileBase + off;
}

// ------------------------- fp32 -> bf16 hi/lo split ------------------------------
__global__ __launch_bounds__(256) void conv_split(
    const float* __restrict__ X, __nv_bfloat16* __restrict__ H,
    __nv_bfloat16* __restrict__ L)
{
    int i = (blockIdx.x * 256 + threadIdx.x) * 4;
    float4 v = *(const float4*)(X + i);
    __nv_bfloat16 h0 = __float2bfloat16(v.x), h1 = __float2bfloat16(v.y);
    __nv_bfloat16 h2 = __float2bfloat16(v.z), h3 = __float2bfloat16(v.w);
    __nv_bfloat16 l0 = __float2bfloat16(v.x - __bfloat162float(h0));
    __nv_bfloat16 l1 = __float2bfloat16(v.y - __bfloat162float(h1));
    __nv_bfloat16 l2 = __float2bfloat16(v.z - __bfloat162float(h2));
    __nv_bfloat16 l3 = __float2bfloat16(v.w - __bfloat162float(h3));
    *(__nv_bfloat162*)(H + i)     = __halves2bfloat162(h0, h1);
    *(__nv_bfloat162*)(H + i + 2) = __halves2bfloat162(h2, h3);
    *(__nv_bfloat162*)(L + i)     = __halves2bfloat162(l0, l1);
    *(__nv_bfloat162*)(L + i + 2) = __halves2bfloat162(l2, l3);
}

// ------------------------- transpose+split device core ---------------------------
__device__ __forceinline__ void wt_tile(
    const float* __restrict__ W, __nv_bfloat16* __restrict__ Th,
    __nv_bfloat16* __restrict__ Tl, int K, int N, int n0, int k0)
{
    __shared__ float t[32][33];
    int tx = threadIdx.x & 31, ty = threadIdx.x >> 5;  // 32 x 8
#pragma unroll
    for (int j = 0; j < 4; j++)
        t[ty + 8 * j][tx] = W[(size_t)(k0 + ty + 8 * j) * N + n0 + tx];
    __syncthreads();
#pragma unroll
    for (int j = 0; j < 4; j++) {
        float v = t[tx][ty + 8 * j];
        __nv_bfloat16 h = __float2bfloat16(v);
        size_t o = (size_t)(n0 + ty + 8 * j) * K + k0 + tx;
        Th[o] = h;
        Tl[o] = __float2bfloat16(v - __bfloat162float(h));
    }
}

// all 4 weight transposes in one launch: 4096 + 1024 + 1024 + 4096 = 10240 blocks
__global__ __launch_bounds__(256) void conv_w_all(
    const float* __restrict__ wq, const float* __restrict__ wk,
    const float* __restrict__ wv, const float* __restrict__ wo,
    __nv_bfloat16* __restrict__ wqh, __nv_bfloat16* __restrict__ wql,
    __nv_bfloat16* __restrict__ wkh, __nv_bfloat16* __restrict__ wkl,
    __nv_bfloat16* __restrict__ wvh, __nv_bfloat16* __restrict__ wvl,
    __nv_bfloat16* __restrict__ woh, __nv_bfloat16* __restrict__ wol)
{
    int b = blockIdx.x;
    if (b < 4096)
        wt_tile(wq, wqh, wql, HIDDEN, QSTR, (b & 63) * 32, (b >> 6) * 32);
    else if (b < 5120) {
        int l = b - 4096;
        wt_tile(wk, wkh, wkl, HIDDEN, KSTR, (l & 15) * 32, (l >> 4) * 32);
    } else if (b < 6144) {
        int l = b - 5120;
        wt_tile(wv, wvh, wvl, HIDDEN, KSTR, (l & 15) * 32, (l >> 4) * 32);
    } else {
        int l = b - 6144;
        wt_tile(wo, woh, wol, QSTR, HIDDEN, (l & 63) * 32, (l >> 6) * 32);
    }
}

// ------------------------- bf16x3 HMMA GEMM core (3-stage) -----------------------
#define GA_BYTES 8192                  // 128x32 bf16
#define GB_BYTES 4096                  // 64x32 bf16
#define GSTAGE   (2 * GA_BYTES + 2 * GB_BYTES)   // 24576
#define G_SMEM   (3 * GSTAGE)                    // 73728

__device__ __forceinline__ void gemm_stage(
    uint32_t st, int k0, int tid, int K,
    const __nv_bfloat16* __restrict__ A0h, const __nv_bfloat16* __restrict__ A0l,
    const __nv_bfloat16* __restrict__ B0h, const __nv_bfloat16* __restrict__ B0l)
{
#pragma unroll
    for (int s2 = 0; s2 < 6; s2++) {
        int i = tid + 256 * s2;
        if (i < 1024) {
            int sp = i >> 9, r = (i >> 2) & 127, x = i & 3;
            const __nv_bfloat16* src = (sp ? A0l : A0h) + (size_t)r * K + k0 + x * 8;
            cp_async16(swz(st + sp * GA_BYTES, r, x), src);
        } else {
            int j = i - 1024;
            int sp = j >> 8, r = (j >> 2) & 63, x = j & 3;
            const __nv_bfloat16* src = (sp ? B0l : B0h) + (size_t)r * K + k0 + x * 8;
            cp_async16(swz(st + 2 * GA_BYTES + sp * GB_BYTES, r, x), src);
        }
    }
    cp_commit();
}

__device__ __forceinline__ void gemm_core(
    const __nv_bfloat16* __restrict__ A0h, const __nv_bfloat16* __restrict__ A0l,
    const __nv_bfloat16* __restrict__ B0h, const __nv_bfloat16* __restrict__ B0l,
    float* __restrict__ C0, int ldc, int K, uint32_t sb)
{
    const int tid  = threadIdx.x;
    const int wid  = tid >> 5;
    const int lane = tid & 31;
    const int mBase = (wid >> 1) * 32;
    const int nBase = (wid & 1) * 32;
    const int lr = lane & 15, lc = lane >> 4;

    float acc[2][4][4];
#pragma unroll
    for (int f = 0; f < 2; f++)
#pragma unroll
        for (int j = 0; j < 4; j++)
#pragma unroll
            for (int x = 0; x < 4; x++) acc[f][j][x] = 0.f;

    const int nChunks = K >> 5;
    gemm_stage(sb, 0, tid, K, A0h, A0l, B0h, B0l);
    gemm_stage(sb + GSTAGE, 32, tid, K, A0h, A0l, B0h, B0l);

    for (int kc = 0; kc < nChunks; kc++) {
        const uint32_t st = sb + (kc % 3) * GSTAGE;
        if (kc + 2 < nChunks) {
            gemm_stage(sb + ((kc + 2) % 3) * GSTAGE, (kc + 2) << 5, tid, K,
                       A0h, A0l, B0h, B0l);
            cp_wait<2>();
        } else if (kc + 1 < nChunks) {
            cp_wait<1>();
        } else {
            cp_wait<0>();
        }
        __syncthreads();

        const uint32_t tAh = st, tAl = st + GA_BYTES;
        const uint32_t tBh = st + 2 * GA_BYTES, tBl = tBh + GB_BYTES;

#pragma unroll
        for (int ks = 0; ks < 2; ks++) {
            const int ch = ks * 2 + lc;
            uint32_t ah[2][4], al[2][4], bb[2][4];
#pragma unroll
            for (int f = 0; f < 2; f++)
                ldsm_x4(ah[f], swz(tAh, mBase + f * 16 + lr, ch));
#pragma unroll
            for (int g = 0; g < 2; g++)
                ldsm_x4(bb[g], swz(tBh, nBase + g * 16 + lr, ch));
#pragma unroll
            for (int f = 0; f < 2; f++)
#pragma unroll
                for (int j = 0; j < 4; j++) {
                    uint32_t bfr[2] = {bb[j >> 1][j & 1], bb[j >> 1][2 + (j & 1)]};
                    mma_bf16(acc[f][j], ah[f], bfr, acc[f][j]);
                }
#pragma unroll
            for (int f = 0; f < 2; f++)
                ldsm_x4(al[f], swz(tAl, mBase + f * 16 + lr, ch));
#pragma unroll
            for (int f = 0; f < 2; f++)
#pragma unroll
                for (int j = 0; j < 4; j++) {
                    uint32_t bfr[2] = {bb[j >> 1][j & 1], bb[j >> 1][2 + (j & 1)]};
                    mma_bf16(acc[f][j], al[f], bfr, acc[f][j]);
                }
#pragma unroll
            for (int g = 0; g < 2; g++)
                ldsm_x4(bb[g], swz(tBl, nBase + g * 16 + lr, ch));
#pragma unroll
            for (int f = 0; f < 2; f++)
#pragma unroll
                for (int j = 0; j < 4; j++) {
                    uint32_t bfr[2] = {bb[j >> 1][j & 1], bb[j >> 1][2 + (j & 1)]};
                    mma_bf16(acc[f][j], ah[f], bfr, acc[f][j]);
                }
        }
        __syncthreads();
    }

    const int erow = lane >> 2;
    const int ecol = (lane & 3) * 2;
#pragma unroll
    for (int f = 0; f < 2; f++) {
        int rl = mBase + f * 16 + erow;
#pragma unroll
        for (int j = 0; j < 4; j++) {
            int cl = nBase + j * 8 + ecol;
            *(float2*)(C0 + (size_t)rl * ldc + cl)       = make_float2(acc[f][j][0], acc[f][j][1]);
            *(float2*)(C0 + (size_t)(rl + 8) * ldc + cl) = make_float2(acc[f][j][2], acc[f][j][3]);
        }
    }
}

// fused QKV projection: grid.x = 48 (32 q blocks, 8 k blocks, 8 v blocks)
__global__ __launch_bounds__(256, 2) void gemm_qkv(
    const __nv_bfloat16* __restrict__ Ah, const __nv_bfloat16* __restrict__ Al,
    const __nv_bfloat16* __restrict__ wqh, const __nv_bfloat16* __restrict__ wql,
    const __nv_bfloat16* __restrict__ wkh, const __nv_bfloat16* __restrict__ wkl,
    const __nv_bfloat16* __restrict__ wvh, const __nv_bfloat16* __restrict__ wvl,
    float* __restrict__ Q, float* __restrict__ K, float* __restrict__ V)
{
    extern __shared__ char smc[];
    const uint32_t sb = smem_u32(smc);
    const int bx = blockIdx.x;
    const int m0 = blockIdx.y * 128;

    const __nv_bfloat16 *Bh, *Bl;
    float* C;
    int n0, ldc;
    if (bx < 32)      { Bh = wqh; Bl = wql; C = Q; n0 = bx * 64;        ldc = QSTR; }
    else if (bx < 40) { Bh = wkh; Bl = wkl; C = K; n0 = (bx - 32) * 64; ldc = KSTR; }
    else              { Bh = wvh; Bl = wvl; C = V; n0 = (bx - 40) * 64; ldc = KSTR; }

    gemm_core(Ah + (size_t)m0 * HIDDEN, Al + (size_t)m0 * HIDDEN,
              Bh + (size_t)n0 * HIDDEN, Bl + (size_t)n0 * HIDDEN,
              C + (size_t)m0 * ldc + n0, ldc, HIDDEN, sb);
}

// generic single GEMM (used for output projection)
__global__ __launch_bounds__(256, 2) void gemm_bf16x3(
    const __nv_bfloat16* __restrict__ Ah, const __nv_bfloat16* __restrict__ Al,
    const __nv_bfloat16* __restrict__ Bh, const __nv_bfloat16* __restrict__ Bl,
    float* __restrict__ C, int M, int N, int K)
{
    extern __shared__ char smc[];
    const uint32_t sb = smem_u32(smc);
    const int m0 = blockIdx.y * 128, n0 = blockIdx.x * 64;
    gemm_core(Ah + (size_t)m0 * K, Al + (size_t)m0 * K,
              Bh + (size_t)n0 * K, Bl + (size_t)n0 * K,
              C + (size_t)m0 * N + n0, N, K, sb);
}

// ------------------------- fused attention prep (one launch) ---------------------
// blocks [0, 8192): rms+rope+split for Q (8 rows each, warp per row)
// blocks [8192, 10240): rms+rope+split for K
// blocks [10240, 12288): V transpose+split (32x32 tiles)
__device__ __forceinline__ void rms_rope_rows(
    const float* __restrict__ in, const float* __restrict__ cosp,
    const float* __restrict__ sinp, const float* __restrict__ w,
    int nh, float outScale, int rowBase,
    __nv_bfloat16* __restrict__ Hh, __nv_bfloat16* __restrict__ Hl)
{
    const int lane = threadIdx.x & 31;
    const int rowIdx = rowBase + (threadIdx.x >> 5);
    const int s = rowIdx / nh;
    const int d0 = lane * 2;

    const float* x = in + (size_t)rowIdx * DHD;
    float2 a = *(const float2*)(x + d0);
    float2 b = *(const float2*)(x + 64 + d0);

    float ss = a.x * a.x + a.y * a.y + b.x * b.x + b.y * b.y;
#pragma unroll
    for (int o = 16; o > 0; o >>= 1) ss += __shfl_xor_sync(0xFFFFFFFFu, ss, o);
    float inv = rsqrtf(ss * (1.0f / DHD) + RMS_EPS);

    float2 wa = *(const float2*)(w + d0);
    float2 wb = *(const float2*)(w + 64 + d0);
    const float* cs = cosp + (size_t)s * DHD;
    const float* sn = sinp + (size_t)s * DHD;
    float2 ca = *(const float2*)(cs + d0), cb = *(const float2*)(cs + 64 + d0);
    float2 sa = *(const float2*)(sn + d0), sb2 = *(const float2*)(sn + 64 + d0);

    float xa0 = a.x * inv * wa.x, xa1 = a.y * inv * wa.y;
    float xb0 = b.x * inv * wb.x, xb1 = b.y * inv * wb.y;
    float oa0 = (xa0 * ca.x - xb0 * sa.x) * outScale;
    float oa1 = (xa1 * ca.y - xb1 * sa.y) * outScale;
    float ob0 = (xb0 * cb.x + xa0 * sb2.x) * outScale;
    float ob1 = (xb1 * cb.y + xa1 * sb2.y) * outScale;

    size_t off = (size_t)rowIdx * DHD + d0;
    __nv_bfloat162 hA = __floats2bfloat162_rn(oa0, oa1);
    __nv_bfloat162 hB = __floats2bfloat162_rn(ob0, ob1);
    __nv_bfloat162 lA = __floats2bfloat162_rn(oa0 - __bfloat162float(hA.x),
                                              oa1 - __bfloat162float(hA.y));
    __nv_bfloat162 lB = __floats2bfloat162_rn(ob0 - __bfloat162float(hB.x),
                                              ob1 - __bfloat162float(hB.y));
    *(__nv_bfloat162*)(Hh + off)      = hA;
    *(__nv_bfloat162*)(Hh + off + 64) = hB;
    *(__nv_bfloat162*)(Hl + off)      = lA;
    *(__nv_bfloat162*)(Hl + off + 64) = lB;
}

__global__ __launch_bounds__(256) void prep_attn(
    const float* __restrict__ qp, const float* __restrict__ kp,
    const float* __restrict__ vp,
    const float* __restrict__ cosp, const float* __restrict__ sinp,
    const float* __restrict__ qnw, const float* __restrict__ knw,
    __nv_bfloat16* __restrict__ qh, __nv_bfloat16* __restrict__ ql,
    __nv_bfloat16* __restrict__ kh, __nv_bfloat16* __restrict__ kl,
    __nv_bfloat16* __restrict__ vth, __nv_bfloat16* __restrict__ vtl)
{
    int b = blockIdx.x;
    if (b < 8192)
        rms_rope_rows(qp, cosp, sinp, qnw, HQ, SM_SCALE, b * 8, qh, ql);
    else if (b < 10240)
        rms_rope_rows(kp, cosp, sinp, knw, HKV, 1.0f, (b - 8192) * 8, kh, kl);
    else {
        int l = b - 10240;   // vT: 16 x 128 tiles of 32x32
        wt_tile(vp, vth, vtl, S_LEN, KSTR, (l & 15) * 32, (l >> 4) * 32);
    }
}

// ------------------------- HMMA causal flash attention (pipelined) ---------------
#define FBM 64
#define FBN 64
#define FSLOT 32768
#define F_SMEM (3 * FSLOT)

__device__ __forceinline__ void flash_load_k(
    uint32_t dst, int tid, int kg0, int hk,
    const __nv_bfloat16* Kh, const __nv_bfloat16* Kl)
{
    const __nv_bfloat16* Ks[2] = {Kh, Kl};
#pragma unroll
    for (int s = 0; s < 16; s++) {
        int i = tid + 128 * s;
        int sp = i >> 10, c = (i >> 8) & 3, r = (i >> 2) & 63, x = i & 3;
        cp_async16(swz(dst + sp * 16384 + c * 4096, r, x),
                   Ks[sp] + ((size_t)(kg0 + r) * HKV + hk) * DHD + c * 32 + x * 8);
    }
}
__device__ __forceinline__ void flash_load_v(
    uint32_t dst, int tid, int kg0, int hk,
    const __nv_bfloat16* Vth, const __nv_bfloat16* Vtl)
{
    const __nv_bfloat16* Vs[2] = {Vth, Vtl};
#pragma unroll
    for (int s = 0; s < 16; s++) {
        int i = tid + 128 * s;
        int sp = i >> 10, kc = (i >> 9) & 1, r = (i >> 2) & 127, x = i & 3;
        cp_async16(swz(dst + sp * 16384 + kc * 8192, r, x),
                   Vs[sp] + (size_t)(hk * DHD + r) * S_LEN + kg0 + kc * 32 + x * 8);
    }
}

__global__ __launch_bounds__(128, 2) void flash_hmma(
    const __nv_bfloat16* __restrict__ Qh, const __nv_bfloat16* __restrict__ Ql,
    const __nv_bfloat16* __restrict__ Kh, const __nv_bfloat16* __restrict__ Kl,
    const __nv_bfloat16* __restrict__ Vth, const __nv_bfloat16* __restrict__ Vtl,
    __nv_bfloat16* __restrict__ Oh, __nv_bfloat16* __restrict__ Ol)
{
    extern __shared__ char smf[];
    const uint32_t sb = smem_u32(smf);
    const int tid = threadIdx.x, wid = tid >> 5, lane = tid & 31;
    const int qt = (int)gridDim.x - 1 - (int)blockIdx.x;   // heavy tiles first
    const int h = blockIdx.y, hk = h >> 2;
    const int qm0 = qt * FBM;
    const int wBase = wid * 16;
    const int lr = lane & 15, lc = lane >> 4;
    const int erow = lane >> 2, q4 = lane & 3;

    const uint32_t kRing[3] = {sb, sb + 2 * FSLOT, sb + FSLOT};
    const uint32_t vRing[3] = {sb + FSLOT, sb, sb + 2 * FSLOT};
    const uint32_t qBase = sb + 2 * FSLOT;

    const __nv_bfloat16* Qs[2] = {Qh, Ql};
#pragma unroll
    for (int s = 0; s < 16; s++) {
        int i = tid + 128 * s;
        int sp = i >> 10, c = (i >> 8) & 3, r = (i >> 2) & 63, x = i & 3;
        cp_async16(swz(qBase + sp * 16384 + c * 4096, r, x),
                   Qs[sp] + ((size_t)(qm0 + r) * HQ + h) * DHD + c * 32 + x * 8);
    }
    flash_load_k(kRing[0], tid, 0, hk, Kh, Kl);
    cp_commit();
    flash_load_v(vRing[0], tid, 0, hk, Vth, Vtl);
    cp_commit();

    uint32_t qfh[8][4], qfl[8][4];
    float oacc[16][4];
#pragma unroll
    for (int jj = 0; jj < 16; jj++)
#pragma unroll
        for (int x = 0; x < 4; x++) oacc[jj][x] = 0.f;
    float m0 = -1e30f, m1 = -1e30f, l0 = 0.f, l1 = 0.f;

    for (int t = 0; t <= qt; t++) {
        const uint32_t kb = kRing[t % 3];
        const uint32_t vb = vRing[t % 3];

        cp_wait<1>();           // K_t (and Q at t=0) complete
        __syncthreads();

        if (t == 0) {
#pragma unroll
            for (int kk = 0; kk < 8; kk++) {
                int c = kk >> 1, x = (kk & 1) * 2 + lc;
                ldsm_x4(qfh[kk], swz(qBase + c * 4096, wBase + lr, x));
                ldsm_x4(qfl[kk], swz(qBase + 16384 + c * 4096, wBase + lr, x));
            }
        }

        // prefetch K_{t+1} BEFORE the S phase so the load overlaps all S mma.
        // (at t=0 the target slot held Q; Q frags were just consumed above)
        if (t < qt) {
            flash_load_k(kRing[(t + 1) % 3], tid, (t + 1) * FBN, hk, Kh, Kl);
            cp_commit();
        }

        float sacc[8][4];
#pragma unroll
        for (int j = 0; j < 8; j++)
#pragma unroll
            for (int x = 0; x < 4; x++) sacc[j][x] = 0.f;

#pragma unroll
        for (int kk = 0; kk < 8; kk++) {
            int c = kk >> 1, x = (kk & 1) * 2 + lc;
            uint32_t kbf[4][4];
#pragma unroll
            for (int g = 0; g < 4; g++)
                ldsm_x4(kbf[g], swz(kb + c * 4096, g * 16 + lr, x));
#pragma unroll
            for (int j = 0; j < 8; j++) {
                uint32_t bf[2] = {kbf[j >> 1][j & 1], kbf[j >> 1][(j & 1) + 2]};
                mma_bf16(sacc[j], qfh[kk], bf, sacc[j]);
            }
#pragma unroll
            for (int j = 0; j < 8; j++) {
                uint32_t bf[2] = {kbf[j >> 1][j & 1], kbf[j >> 1][(j & 1) + 2]};
                mma_bf16(sacc[j], qfl[kk], bf, sacc[j]);
            }
#pragma unroll
            for (int g = 0; g < 4; g++)
                ldsm_x4(kbf[g], swz(kb + 16384 + c * 4096, g * 16 + lr, x));
#pragma unroll
            for (int j = 0; j < 8; j++) {
                uint32_t bf[2] = {kbf[j >> 1][j & 1], kbf[j >> 1][(j & 1) + 2]};
                mma_bf16(sacc[j], qfh[kk], bf, sacc[j]);
            }
        }

        if (t == qt) {
            int row0 = qm0 + wBase + erow, row1 = row0 + 8;
            int colb = t * FBN + q4 * 2;
#pragma unroll
            for (int j = 0; j < 8; j++) {
                int c0 = colb + j * 8, c1 = c0 + 1;
                if (c0 > row0) sacc[j][0] = -1e30f;
                if (c1 > row0) sacc[j][1] = -1e30f;
                if (c0 > row1) sacc[j][2] = -1e30f;
                if (c1 > row1) sacc[j][3] = -1e30f;
            }
        }

        float mx0 = -1e30f, mx1 = -1e30f;
#pragma unroll
        for (int j = 0; j < 8; j++) {
            mx0 = fmaxf(mx0, fmaxf(sacc[j][0], sacc[j][1]));
            mx1 = fmaxf(mx1, fmaxf(sacc[j][2], sacc[j][3]));
        }
        mx0 = fmaxf(mx0, __shfl_xor_sync(0xFFFFFFFFu, mx0, 1));
        mx0 = fmaxf(mx0, __shfl_xor_sync(0xFFFFFFFFu, mx0, 2));
        mx1 = fmaxf(mx1, __shfl_xor_sync(0xFFFFFFFFu, mx1, 1));
        mx1 = fmaxf(mx1, __shfl_xor_sync(0xFFFFFFFFu, mx1, 2));
        float mn0 = fmaxf(m0, mx0), mn1 = fmaxf(m1, mx1);
        float a0 = __expf(m0 - mn0), a1 = __expf(m1 - mn1);
        float s0 = 0.f, s1 = 0.f;
#pragma unroll
        for (int j = 0; j < 8; j++) {
            float p0 = __expf(sacc[j][0] - mn0); sacc[j][0] = p0; s0 += p0;
            float p1 = __expf(sacc[j][1] - mn0); sacc[j][1] = p1; s0 += p1;
            float p2 = __expf(sacc[j][2] - mn1); sacc[j][2] = p2; s1 += p2;
            float p3 = __expf(sacc[j][3] - mn1); sacc[j][3] = p3; s1 += p3;
        }
        s0 += __shfl_xor_sync(0xFFFFFFFFu, s0, 1);
        s0 += __shfl_xor_sync(0xFFFFFFFFu, s0, 2);
        s1 += __shfl_xor_sync(0xFFFFFFFFu, s1, 1);
        s1 += __shfl_xor_sync(0xFFFFFFFFu, s1, 2);
        l0 = l0 * a0 + s0;
        l1 = l1 * a1 + s1;
        m0 = mn0; m1 = mn1;
#pragma unroll
        for (int jj = 0; jj < 16; jj++) {
            oacc[jj][0] *= a0; oacc[jj][1] *= a0;
            oacc[jj][2] *= a1; oacc[jj][3] *= a1;
        }

        // wait for V_t (K_{t+1} may stay in flight)
        if (t < qt) cp_wait<1>(); else cp_wait<0>();
        __syncthreads();        // all warps done reading K_t (S phase)

        // prefetch V_{t+1} into K_t's slot (overlaps PV phase)
        if (t < qt) {
            flash_load_v(vRing[(t + 1) % 3], tid, (t + 1) * FBN, hk, Vth, Vtl);
            cp_commit();
        }

#pragma unroll
        for (int tt = 0; tt < 4; tt++) {
            uint32_t ph[4], pl[4];
            {
                __nv_bfloat162 v0 = __floats2bfloat162_rn(sacc[2*tt][0],   sacc[2*tt][1]);
                __nv_bfloat162 v1 = __floats2bfloat162_rn(sacc[2*tt][2],   sacc[2*tt][3]);
                __nv_bfloat162 v2 = __floats2bfloat162_rn(sacc[2*tt+1][0], sacc[2*tt+1][1]);
                __nv_bfloat162 v3 = __floats2bfloat162_rn(sacc[2*tt+1][2], sacc[2*tt+1][3]);
                ph[0] = *(uint32_t*)&v0; ph[1] = *(uint32_t*)&v1;
                ph[2] = *(uint32_t*)&v2; ph[3] = *(uint32_t*)&v3;
                __nv_bfloat162 w0 = __floats2bfloat162_rn(
                    sacc[2*tt][0]   - __bfloat162float(v0.x), sacc[2*tt][1]   - __bfloat162float(v0.y));
                __nv_bfloat162 w1 = __floats2bfloat162_rn(
                    sacc[2*tt][2]   - __bfloat162float(v1.x), sacc[2*tt][3]   - __bfloat162float(v1.y));
                __nv_bfloat162 w2 = __floats2bfloat162_rn(
                    sacc[2*tt+1][0] - __bfloat162float(v2.x), sacc[2*tt+1][1] - __bfloat162float(v2.y));
                __nv_bfloat162 w3 = __floats2bfloat162_rn(
                    sacc[2*tt+1][2] - __bfloat162float(v3.x), sacc[2*tt+1][3] - __bfloat162float(v3.y));
                pl[0] = *(uint32_t*)&w0; pl[1] = *(uint32_t*)&w1;
                pl[2] = *(uint32_t*)&w2; pl[3] = *(uint32_t*)&w3;
            }
            int kc = tt >> 1, x = (tt & 1) * 2 + lc;
            uint32_t vbf[8][4];
#pragma unroll
            for (int g = 0; g < 8; g++)
                ldsm_x4(vbf[g], swz(vb + kc * 8192, g * 16 + lr, x));
#pragma unroll
            for (int jj = 0; jj < 16; jj++) {
                uint32_t bf[2] = {vbf[jj >> 1][jj & 1], vbf[jj >> 1][(jj & 1) + 2]};
                mma_bf16(oacc[jj], ph, bf, oacc[jj]);
            }
#pragma unroll
            for (int jj = 0; jj < 16; jj++) {
                uint32_t bf[2] = {vbf[jj >> 1][jj & 1], vbf[jj >> 1][(jj & 1) + 2]};
                mma_bf16(oacc[jj], pl, bf, oacc[jj]);
            }
#pragma unroll
            for (int g = 0; g < 8; g++)
                ldsm_x4(vbf[g], swz(vb + 16384 + kc * 8192, g * 16 + lr, x));
#pragma unroll
            for (int jj = 0; jj < 16; jj++) {
                uint32_t bf[2] = {vbf[jj >> 1][jj & 1], vbf[jj >> 1][(jj & 1) + 2]};
                mma_bf16(oacc[jj], ph, bf, oacc[jj]);
            }
        }
    }

    float il0 = 1.0f / l0, il1 = 1.0f / l1;
    int row0 = qm0 + wBase + erow;
#pragma unroll
    for (int jj = 0; jj < 16; jj++) {
        int col = jj * 8 + q4 * 2;
        {
            float o0 = oacc[jj][0] * il0, o1 = oacc[jj][1] * il0;
            __nv_bfloat162 hh = __floats2bfloat162_rn(o0, o1);
            __nv_bfloat162 ll = __floats2bfloat162_rn(o0 - __bfloat162float(hh.x),
                                                      o1 - __bfloat162float(hh.y));
            size_t off = (size_t)row0 * QSTR + h * DHD + col;
            *(__nv_bfloat162*)(Oh + off) = hh;
            *(__nv_bfloat162*)(Ol + off) = ll;
        }
        {
            float o0 = oacc[jj][2] * il1, o1 = oacc[jj][3] * il1;
            __nv_bfloat162 hh = __floats2bfloat162_rn(o0, o1);
            __nv_bfloat162 ll = __floats2bfloat162_rn(o0 - __bfloat162float(hh.x),
                                                      o1 - __bfloat162float(hh.y));
            size_t off = (size_t)(row0 + 8) * QSTR + h * DHD + col;
            *(__nv_bfloat162*)(Oh + off) = hh;
            *(__nv_bfloat162*)(Ol + off) = ll;
        }
    }
}

// ------------------------- launch -----------------------------------------------
extern "C" void kernel_launch(void* const* d_in, const int* in_sizes, int n_in,
                              void* d_out, int out_size)
{
    (void)in_sizes; (void)n_in; (void)out_size;
    const float* hs   = (const float*)d_in[0];
    const float* cosp = (const float*)d_in[1];
    const float* sinp = (const float*)d_in[2];
    const float* wq   = (const float*)d_in[3];
    const float* wk   = (const float*)d_in[4];
    const float* wv   = (const float*)d_in[5];
    const float* wo   = (const float*)d_in[6];
    const float* qnw  = (const float*)d_in[7];
    const float* knw  = (const float*)d_in[8];
    float* out = (float*)d_out;

    float *qp, *kp, *vp;
    cudaGetSymbolAddress((void**)&qp, g_q);
    cudaGetSymbolAddress((void**)&kp, g_k);
    cudaGetSymbolAddress((void**)&vp, g_v);
    __nv_bfloat16 *hsh, *hsl, *ath, *atl;
    __nv_bfloat16 *qh, *ql, *kh, *kl, *vth, *vtl;
    __nv_bfloat16 *wqh, *wql, *wkh, *wkl, *wvh, *wvl, *woh, *wol;
    cudaGetSymbolAddress((void**)&hsh, g_hs_h);
    cudaGetSymbolAddress((void**)&hsl, g_hs_l);
    cudaGetSymbolAddress((void**)&ath, g_at_h);
    cudaGetSymbolAddress((void**)&atl, g_at_l);
    cudaGetSymbolAddress((void**)&qh, g_qh);
    cudaGetSymbolAddress((void**)&ql, g_ql);
    cudaGetSymbolAddress((void**)&kh, g_kh);
    cudaGetSymbolAddress((void**)&kl, g_kl);
    cudaGetSymbolAddress((void**)&vth, g_vth);
    cudaGetSymbolAddress((void**)&vtl, g_vtl);
    cudaGetSymbolAddress((void**)&wqh, g_wq_h);
    cudaGetSymbolAddress((void**)&wql, g_wq_l);
    cudaGetSymbolAddress((void**)&wkh, g_wk_h);
    cudaGetSymbolAddress((void**)&wkl, g_wk_l);
    cudaGetSymbolAddress((void**)&wvh, g_wv_h);
    cudaGetSymbolAddress((void**)&wvl, g_wv_l);
    cudaGetSymbolAddress((void**)&woh, g_wo_h);
    cudaGetSymbolAddress((void**)&wol, g_wo_l);

    cudaFuncSetAttribute(gemm_qkv, cudaFuncAttributeMaxDynamicSharedMemorySize, G_SMEM);
    cudaFuncSetAttribute(gemm_bf16x3, cudaFuncAttributeMaxDynamicSharedMemorySize, G_SMEM);
    cudaFuncSetAttribute(flash_hmma, cudaFuncAttributeMaxDynamicSharedMemorySize, F_SMEM);

    // 1) hidden_states split
    conv_split<<<(S_LEN * HIDDEN) / 1024, 256>>>(hs, hsh, hsl);
    // 2) all weight transposes (one launch)
    conv_w_all<<<10240, 256>>>(wq, wk, wv, wo,
                               wqh, wql, wkh, wkl, wvh, wvl, woh, wol);
    // 3) fused QKV projection
    gemm_qkv<<<dim3(48, S_LEN / 128), 256, G_SMEM>>>(
        hsh, hsl, wqh, wql, wkh, wkl, wvh, wvl, qp, kp, vp);
    // 4) attention prep: rms+rope Q, rms+rope K, V transpose (one launch)
    prep_attn<<<12288, 256>>>(qp, kp, vp, cosp, sinp, qnw, knw,
                              qh, ql, kh, kl, vth, vtl);
    // 5) causal flash attention
    flash_hmma<<<dim3(S_LEN / FBM, HQ), 128, F_SMEM>>>(
        qh, ql, kh, kl, vth, vtl, ath, atl);
    // 6) output projection
    gemm_bf16x3<<<dim3(HIDDEN / 64, S_LEN / 128), 256, G_SMEM>>>(
        ath, atl, woh, wol, out, S_LEN, HIDDEN, QSTR);
}

// round 9
// speedup vs baseline: 1.0025x; 1.0025x over previous
#include <cuda_runtime.h>
#include <cuda_bf16.h>
#include <math.h>
#include <stdint.h>

#define S_LEN 4096
#define HIDDEN 2048
#define HQ 16
#define HKV 4
#define DHD 128
#define QSTR (HQ*DHD)    // 2048
#define KSTR (HKV*DHD)   // 512
#define RMS_EPS 1e-6f
#define SM_SCALE 0.08838834764831845f  // 128^-0.5

// ------------------------- scratch (static device globals) ----------------------
__device__ float g_q[S_LEN * QSTR];
__device__ float g_k[S_LEN * KSTR];
__device__ float g_v[S_LEN * KSTR];

__device__ __nv_bfloat16 g_hs_h[S_LEN * HIDDEN];
__device__ __nv_bfloat16 g_hs_l[S_LEN * HIDDEN];
__device__ __nv_bfloat16 g_at_h[S_LEN * QSTR];
__device__ __nv_bfloat16 g_at_l[S_LEN * QSTR];
__device__ __nv_bfloat16 g_qh[S_LEN * QSTR];
__device__ __nv_bfloat16 g_ql[S_LEN * QSTR];
__device__ __nv_bfloat16 g_kh[S_LEN * KSTR];
__device__ __nv_bfloat16 g_kl[S_LEN * KSTR];
__device__ __nv_bfloat16 g_vth[KSTR * S_LEN];   // [hk*128+d][s]
__device__ __nv_bfloat16 g_vtl[KSTR * S_LEN];
__device__ __nv_bfloat16 g_wq_h[QSTR * HIDDEN];
__device__ __nv_bfloat16 g_wq_l[QSTR * HIDDEN];
__device__ __nv_bfloat16 g_wk_h[KSTR * HIDDEN];
__device__ __nv_bfloat16 g_wk_l[KSTR * HIDDEN];
__device__ __nv_bfloat16 g_wv_h[KSTR * HIDDEN];
__device__ __nv_bfloat16 g_wv_l[KSTR * HIDDEN];
__device__ __nv_bfloat16 g_wo_h[HIDDEN * QSTR];
__device__ __nv_bfloat16 g_wo_l[HIDDEN * QSTR];

// ------------------------- helpers ----------------------------------------------
__device__ __forceinline__ uint32_t smem_u32(const void* p) {
    uint32_t a;
    asm("{ .reg .u64 t; cvta.to.shared.u64 t, %1; cvt.u32.u64 %0, t; }" : "=r"(a) : "l"(p));
    return a;
}
__device__ __forceinline__ void ldsm_x4(uint32_t* r, uint32_t addr) {
    asm volatile("ldmatrix.sync.aligned.m8n8.x4.shared.b16 {%0,%1,%2,%3}, [%4];"
                 : "=r"(r[0]), "=r"(r[1]), "=r"(r[2]), "=r"(r[3]) : "r"(addr));
}
__device__ __forceinline__ void mma_bf16(float* d, const uint32_t* a, const uint32_t* b,
                                         const float* c) {
    asm volatile(
        "mma.sync.aligned.m16n8k16.row.col.f32.bf16.bf16.f32 "
        "{%0,%1,%2,%3}, {%4,%5,%6,%7}, {%8,%9}, {%10,%11,%12,%13};"
        : "=f"(d[0]), "=f"(d[1]), "=f"(d[2]), "=f"(d[3])
        : "r"(a[0]), "r"(a[1]), "r"(a[2]), "r"(a[3]),
          "r"(b[0]), "r"(b[1]),
          "f"(c[0]), "f"(c[1]), "f"(c[2]), "f"(c[3]));
}
__device__ __forceinline__ void cp_async16(uint32_t dst, const void* src) {
    asm volatile("cp.async.cg.shared.global [%0], [%1], 16;" :: "r"(dst), "l"(src) : "memory");
}
__device__ __forceinline__ void cp_commit() {
    asm volatile("cp.async.commit_group;" ::: "memory");
}
template<int N> __device__ __forceinline__ void cp_wait() {
    asm volatile("cp.async.wait_group %0;" :: "n"(N) : "memory");
}
// logical tile rows of 64B (32 bf16) with XOR swizzle for conflict-free ldmatrix
__device__ __forceinline__ uint32_t swz(uint32_t tileBase, int r, int c) {
    uint32_t off = r * 64 + c * 16;
    off ^= ((off >> 7) & 7) << 4;
    return tileBase + off;
}

// ------------------------- transpose+split device core ---------------------------
__device__ __forceinline__ void wt_tile(
    const float* __restrict__ W, __nv_bfloat16* __restrict__ Th,
    __nv_bfloat16* __restrict__ Tl, int K, int N, int n0, int k0)
{
    __shared__ float t[32][33];
    int tx = threadIdx.x & 31, ty = threadIdx.x >> 5;  // 32 x 8
#pragma unroll
    for (int j = 0; j < 4; j++)
        t[ty + 8 * j][tx] = W[(size_t)(k0 + ty + 8 * j) * N + n0 + tx];
    __syncthreads();
#pragma unroll
    for (int j = 0; j < 4; j++) {
        float v = t[tx][ty + 8 * j];
        __nv_bfloat16 h = __float2bfloat16(v);
        size_t o = (size_t)(n0 + ty + 8 * j) * K + k0 + tx;
        Th[o] = h;
        Tl[o] = __float2bfloat16(v - __bfloat162float(h));
    }
}

// merged input prep: hs split (8192 blocks) + all 4 weight transposes (10240)
__global__ __launch_bounds__(256) void prep_inputs(
    const float* __restrict__ hs,
    const float* __restrict__ wq, const float* __restrict__ wk,
    const float* __restrict__ wv, const float* __restrict__ wo,
    __nv_bfloat16* __restrict__ hsh, __nv_bfloat16* __restrict__ hsl,
    __nv_bfloat16* __restrict__ wqh, __nv_bfloat16* __restrict__ wql,
    __nv_bfloat16* __restrict__ wkh, __nv_bfloat16* __restrict__ wkl,
    __nv_bfloat16* __restrict__ wvh, __nv_bfloat16* __restrict__ wvl,
    __nv_bfloat16* __restrict__ woh, __nv_bfloat16* __restrict__ wol)
{
    int b = blockIdx.x;
    if (b < 8192) {
        int i = (b * 256 + threadIdx.x) * 4;
        float4 v = *(const float4*)(hs + i);
        __nv_bfloat16 h0 = __float2bfloat16(v.x), h1 = __float2bfloat16(v.y);
        __nv_bfloat16 h2 = __float2bfloat16(v.z), h3 = __float2bfloat16(v.w);
        __nv_bfloat16 l0 = __float2bfloat16(v.x - __bfloat162float(h0));
        __nv_bfloat16 l1 = __float2bfloat16(v.y - __bfloat162float(h1));
        __nv_bfloat16 l2 = __float2bfloat16(v.z - __bfloat162float(h2));
        __nv_bfloat16 l3 = __float2bfloat16(v.w - __bfloat162float(h3));
        *(__nv_bfloat162*)(hsh + i)     = __halves2bfloat162(h0, h1);
        *(__nv_bfloat162*)(hsh + i + 2) = __halves2bfloat162(h2, h3);
        *(__nv_bfloat162*)(hsl + i)     = __halves2bfloat162(l0, l1);
        *(__nv_bfloat162*)(hsl + i + 2) = __halves2bfloat162(l2, l3);
        return;
    }
    b -= 8192;
    if (b < 4096)
        wt_tile(wq, wqh, wql, HIDDEN, QSTR, (b & 63) * 32, (b >> 6) * 32);
    else if (b < 5120) {
        int l = b - 4096;
        wt_tile(wk, wkh, wkl, HIDDEN, KSTR, (l & 15) * 32, (l >> 4) * 32);
    } else if (b < 6144) {
        int l = b - 5120;
        wt_tile(wv, wvh, wvl, HIDDEN, KSTR, (l & 15) * 32, (l >> 4) * 32);
    } else {
        int l = b - 6144;
        wt_tile(wo, woh, wol, QSTR, HIDDEN, (l & 63) * 32, (l >> 6) * 32);
    }
}

// ------------------------- bf16x3 HMMA GEMM core (K-chunk 64) --------------------
// CTA 128x64, warp tile 32x32, 8 warps. Stage = 64-wide K chunk in two 32-wide
// swizzled subtiles. Double-buffered (96 KB), 2 CTAs/SM. Halved barrier count.
#define GA_SUB 8192                    // 128x32 bf16 subtile
#define GB_SUB 4096                    // 64x32 bf16 subtile
#define GSTAGE 49152                   // 4*GA_SUB + 4*GB_SUB
#define G_SMEM (2 * GSTAGE)            // 98304

__device__ __forceinline__ void gemm_stage(
    uint32_t st, int k0, int tid, int K,
    const __nv_bfloat16* __restrict__ A0h, const __nv_bfloat16* __restrict__ A0l,
    const __nv_bfloat16* __restrict__ B0h, const __nv_bfloat16* __restrict__ B0l)
{
#pragma unroll
    for (int s2 = 0; s2 < 12; s2++) {
        int i = tid + 256 * s2;
        if (i < 2048) {
            int idx = i >> 9;               // 0..3 : Ah0, Ah1, Al0, Al1
            int r = (i >> 2) & 127, x = i & 3;
            const __nv_bfloat16* base = (idx >> 1) ? A0l : A0h;
            cp_async16(swz(st + idx * GA_SUB, r, x),
                       base + (size_t)r * K + k0 + (idx & 1) * 32 + x * 8);
        } else {
            int j = i - 2048;
            int idx = j >> 8;               // 0..3 : Bh0, Bh1, Bl0, Bl1
            int r = (j >> 2) & 63, x = j & 3;
            const __nv_bfloat16* base = (idx >> 1) ? B0l : B0h;
            cp_async16(swz(st + 4 * GA_SUB + idx * GB_SUB, r, x),
                       base + (size_t)r * K + k0 + (idx & 1) * 32 + x * 8);
        }
    }
    cp_commit();
}

__device__ __forceinline__ void gemm_core(
    const __nv_bfloat16* __restrict__ A0h, const __nv_bfloat16* __restrict__ A0l,
    const __nv_bfloat16* __restrict__ B0h, const __nv_bfloat16* __restrict__ B0l,
    float* __restrict__ C0, int ldc, int K, uint32_t sb)
{
    const int tid  = threadIdx.x;
    const int wid  = tid >> 5;
    const int lane = tid & 31;
    const int mBase = (wid >> 1) * 32;
    const int nBase = (wid & 1) * 32;
    const int lr = lane & 15, lc = lane >> 4;

    float acc[2][4][4];
#pragma unroll
    for (int f = 0; f < 2; f++)
#pragma unroll
        for (int j = 0; j < 4; j++)
#pragma unroll
            for (int x = 0; x < 4; x++) acc[f][j][x] = 0.f;

    const int nChunks = K >> 6;
    gemm_stage(sb, 0, tid, K, A0h, A0l, B0h, B0l);

    for (int kc = 0; kc < nChunks; kc++) {
        const uint32_t st = sb + (kc & 1) * GSTAGE;
        if (kc + 1 < nChunks) {
            gemm_stage(sb + ((kc + 1) & 1) * GSTAGE, (kc + 1) << 6, tid, K,
                       A0h, A0l, B0h, B0l);
            cp_wait<1>();
        } else {
            cp_wait<0>();
        }
        __syncthreads();

#pragma unroll
        for (int s16 = 0; s16 < 4; s16++) {
            const int sub = s16 >> 1;
            const int ch  = (s16 & 1) * 2 + lc;
            const uint32_t tAh = st + sub * GA_SUB;
            const uint32_t tAl = st + 2 * GA_SUB + sub * GA_SUB;
            const uint32_t tBh = st + 4 * GA_SUB + sub * GB_SUB;
            const uint32_t tBl = st + 4 * GA_SUB + 2 * GB_SUB + sub * GB_SUB;

            uint32_t ah[2][4], al[2][4], bb[2][4];
#pragma unroll
            for (int f = 0; f < 2; f++)
                ldsm_x4(ah[f], swz(tAh, mBase + f * 16 + lr, ch));
#pragma unroll
            for (int g = 0; g < 2; g++)
                ldsm_x4(bb[g], swz(tBh, nBase + g * 16 + lr, ch));
#pragma unroll
            for (int f = 0; f < 2; f++)
#pragma unroll
                for (int j = 0; j < 4; j++) {
                    uint32_t bfr[2] = {bb[j >> 1][j & 1], bb[j >> 1][2 + (j & 1)]};
                    mma_bf16(acc[f][j], ah[f], bfr, acc[f][j]);
                }
#pragma unroll
            for (int f = 0; f < 2; f++)
                ldsm_x4(al[f], swz(tAl, mBase + f * 16 + lr, ch));
#pragma unroll
            for (int f = 0; f < 2; f++)
#pragma unroll
                for (int j = 0; j < 4; j++) {
                    uint32_t bfr[2] = {bb[j >> 1][j & 1], bb[j >> 1][2 + (j & 1)]};
                    mma_bf16(acc[f][j], al[f], bfr, acc[f][j]);
                }
#pragma unroll
            for (int g = 0; g < 2; g++)
                ldsm_x4(bb[g], swz(tBl, nBase + g * 16 + lr, ch));
#pragma unroll
            for (int f = 0; f < 2; f++)
#pragma unroll
                for (int j = 0; j < 4; j++) {
                    uint32_t bfr[2] = {bb[j >> 1][j & 1], bb[j >> 1][2 + (j & 1)]};
                    mma_bf16(acc[f][j], ah[f], bfr, acc[f][j]);
                }
        }
        __syncthreads();
    }

    const int erow = lane >> 2;
    const int ecol = (lane & 3) * 2;
#pragma unroll
    for (int f = 0; f < 2; f++) {
        int rl = mBase + f * 16 + erow;
#pragma unroll
        for (int j = 0; j < 4; j++) {
            int cl = nBase + j * 8 + ecol;
            *(float2*)(C0 + (size_t)rl * ldc + cl)       = make_float2(acc[f][j][0], acc[f][j][1]);
            *(float2*)(C0 + (size_t)(rl + 8) * ldc + cl) = make_float2(acc[f][j][2], acc[f][j][3]);
        }
    }
}

// fused QKV projection: grid.x = 48 (32 q blocks, 8 k blocks, 8 v blocks)
__global__ __launch_bounds__(256, 2) void gemm_qkv(
    const __nv_bfloat16* __restrict__ Ah, const __nv_bfloat16* __restrict__ Al,
    const __nv_bfloat16* __restrict__ wqh, const __nv_bfloat16* __restrict__ wql,
    const __nv_bfloat16* __restrict__ wkh, const __nv_bfloat16* __restrict__ wkl,
    const __nv_bfloat16* __restrict__ wvh, const __nv_bfloat16* __restrict__ wvl,
    float* __restrict__ Q, float* __restrict__ K, float* __restrict__ V)
{
    extern __shared__ char smc[];
    const uint32_t sb = smem_u32(smc);
    const int bx = blockIdx.x;
    const int m0 = blockIdx.y * 128;

    const __nv_bfloat16 *Bh, *Bl;
    float* C;
    int n0, ldc;
    if (bx < 32)      { Bh = wqh; Bl = wql; C = Q; n0 = bx * 64;        ldc = QSTR; }
    else if (bx < 40) { Bh = wkh; Bl = wkl; C = K; n0 = (bx - 32) * 64; ldc = KSTR; }
    else              { Bh = wvh; Bl = wvl; C = V; n0 = (bx - 40) * 64; ldc = KSTR; }

    gemm_core(Ah + (size_t)m0 * HIDDEN, Al + (size_t)m0 * HIDDEN,
              Bh + (size_t)n0 * HIDDEN, Bl + (size_t)n0 * HIDDEN,
              C + (size_t)m0 * ldc + n0, ldc, HIDDEN, sb);
}

// generic single GEMM (used for output projection)
__global__ __launch_bounds__(256, 2) void gemm_bf16x3(
    const __nv_bfloat16* __restrict__ Ah, const __nv_bfloat16* __restrict__ Al,
    const __nv_bfloat16* __restrict__ Bh, const __nv_bfloat16* __restrict__ Bl,
    float* __restrict__ C, int M, int N, int K)
{
    extern __shared__ char smc[];
    const uint32_t sb = smem_u32(smc);
    const int m0 = blockIdx.y * 128, n0 = blockIdx.x * 64;
    gemm_core(Ah + (size_t)m0 * K, Al + (size_t)m0 * K,
              Bh + (size_t)n0 * K, Bl + (size_t)n0 * K,
              C + (size_t)m0 * N + n0, N, K, sb);
}

// ------------------------- fused attention prep (one launch) ---------------------
__device__ __forceinline__ void rms_rope_rows(
    const float* __restrict__ in, const float* __restrict__ cosp,
    const float* __restrict__ sinp, const float* __restrict__ w,
    int nh, float outScale, int rowBase,
    __nv_bfloat16* __restrict__ Hh, __nv_bfloat16* __restrict__ Hl)
{
    const int lane = threadIdx.x & 31;
    const int rowIdx = rowBase + (threadIdx.x >> 5);
    const int s = rowIdx / nh;
    const int d0 = lane * 2;

    const float* x = in + (size_t)rowIdx * DHD;
    float2 a = *(const float2*)(x + d0);
    float2 b = *(const float2*)(x + 64 + d0);

    float ss = a.x * a.x + a.y * a.y + b.x * b.x + b.y * b.y;
#pragma unroll
    for (int o = 16; o > 0; o >>= 1) ss += __shfl_xor_sync(0xFFFFFFFFu, ss, o);
    float inv = rsqrtf(ss * (1.0f / DHD) + RMS_EPS);

    float2 wa = *(const float2*)(w + d0);
    float2 wb = *(const float2*)(w + 64 + d0);
    const float* cs = cosp + (size_t)s * DHD;
    const float* sn = sinp + (size_t)s * DHD;
    float2 ca = *(const float2*)(cs + d0), cb = *(const float2*)(cs + 64 + d0);
    float2 sa = *(const float2*)(sn + d0), sb2 = *(const float2*)(sn + 64 + d0);

    float xa0 = a.x * inv * wa.x, xa1 = a.y * inv * wa.y;
    float xb0 = b.x * inv * wb.x, xb1 = b.y * inv * wb.y;
    float oa0 = (xa0 * ca.x - xb0 * sa.x) * outScale;
    float oa1 = (xa1 * ca.y - xb1 * sa.y) * outScale;
    float ob0 = (xb0 * cb.x + xa0 * sb2.x) * outScale;
    float ob1 = (xb1 * cb.y + xa1 * sb2.y) * outScale;

    size_t off = (size_t)rowIdx * DHD + d0;
    __nv_bfloat162 hA = __floats2bfloat162_rn(oa0, oa1);
    __nv_bfloat162 hB = __floats2bfloat162_rn(ob0, ob1);
    __nv_bfloat162 lA = __floats2bfloat162_rn(oa0 - __bfloat162float(hA.x),
                                              oa1 - __bfloat162float(hA.y));
    __nv_bfloat162 lB = __floats2bfloat162_rn(ob0 - __bfloat162float(hB.x),
                                              ob1 - __bfloat162float(hB.y));
    *(__nv_bfloat162*)(Hh + off)      = hA;
    *(__nv_bfloat162*)(Hh + off + 64) = hB;
    *(__nv_bfloat162*)(Hl + off)      = lA;
    *(__nv_bfloat162*)(Hl + off + 64) = lB;
}

__global__ __launch_bounds__(256) void prep_attn(
    const float* __restrict__ qp, const float* __restrict__ kp,
    const float* __restrict__ vp,
    const float* __restrict__ cosp, const float* __restrict__ sinp,
    const float* __restrict__ qnw, const float* __restrict__ knw,
    __nv_bfloat16* __restrict__ qh, __nv_bfloat16* __restrict__ ql,
    __nv_bfloat16* __restrict__ kh, __nv_bfloat16* __restrict__ kl,
    __nv_bfloat16* __restrict__ vth, __nv_bfloat16* __restrict__ vtl)
{
    int b = blockIdx.x;
    if (b < 8192)
        rms_rope_rows(qp, cosp, sinp, qnw, HQ, SM_SCALE, b * 8, qh, ql);
    else if (b < 10240)
        rms_rope_rows(kp, cosp, sinp, knw, HKV, 1.0f, (b - 8192) * 8, kh, kl);
    else {
        int l = b - 10240;   // vT: 16 x 128 tiles of 32x32
        wt_tile(vp, vth, vtl, S_LEN, KSTR, (l & 15) * 32, (l >> 4) * 32);
    }
}

// ------------------------- HMMA causal flash attention (pipelined) ---------------
#define FBM 64
#define FBN 64
#define FSLOT 32768
#define F_SMEM (3 * FSLOT)

__device__ __forceinline__ void flash_load_k(
    uint32_t dst, int tid, int kg0, int hk,
    const __nv_bfloat16* Kh, const __nv_bfloat16* Kl)
{
    const __nv_bfloat16* Ks[2] = {Kh, Kl};
#pragma unroll
    for (int s = 0; s < 16; s++) {
        int i = tid + 128 * s;
        int sp = i >> 10, c = (i >> 8) & 3, r = (i >> 2) & 63, x = i & 3;
        cp_async16(swz(dst + sp * 16384 + c * 4096, r, x),
                   Ks[sp] + ((size_t)(kg0 + r) * HKV + hk) * DHD + c * 32 + x * 8);
    }
}
__device__ __forceinline__ void flash_load_v(
    uint32_t dst, int tid, int kg0, int hk,
    const __nv_bfloat16* Vth, const __nv_bfloat16* Vtl)
{
    const __nv_bfloat16* Vs[2] = {Vth, Vtl};
#pragma unroll
    for (int s = 0; s < 16; s++) {
        int i = tid + 128 * s;
        int sp = i >> 10, kc = (i >> 9) & 1, r = (i >> 2) & 127, x = i & 3;
        cp_async16(swz(dst + sp * 16384 + kc * 8192, r, x),
                   Vs[sp] + (size_t)(hk * DHD + r) * S_LEN + kg0 + kc * 32 + x * 8);
    }
}

__global__ __launch_bounds__(128, 2) void flash_hmma(
    const __nv_bfloat16* __restrict__ Qh, const __nv_bfloat16* __restrict__ Ql,
    const __nv_bfloat16* __restrict__ Kh, const __nv_bfloat16* __restrict__ Kl,
    const __nv_bfloat16* __restrict__ Vth, const __nv_bfloat16* __restrict__ Vtl,
    __nv_bfloat16* __restrict__ Oh, __nv_bfloat16* __restrict__ Ol)
{
    extern __shared__ char smf[];
    const uint32_t sb = smem_u32(smf);
    const int tid = threadIdx.x, wid = tid >> 5, lane = tid & 31;
    const int qt = (int)gridDim.x - 1 - (int)blockIdx.x;   // heavy tiles first
    const int h = blockIdx.y, hk = h >> 2;
    const int qm0 = qt * FBM;
    const int wBase = wid * 16;
    const int lr = lane & 15, lc = lane >> 4;
    const int erow = lane >> 2, q4 = lane & 3;

    const uint32_t kRing[3] = {sb, sb + 2 * FSLOT, sb + FSLOT};
    const uint32_t vRing[3] = {sb + FSLOT, sb, sb + 2 * FSLOT};
    const uint32_t qBase = sb + 2 * FSLOT;

    const __nv_bfloat16* Qs[2] = {Qh, Ql};
#pragma unroll
    for (int s = 0; s < 16; s++) {
        int i = tid + 128 * s;
        int sp = i >> 10, c = (i >> 8) & 3, r = (i >> 2) & 63, x = i & 3;
        cp_async16(swz(qBase + sp * 16384 + c * 4096, r, x),
                   Qs[sp] + ((size_t)(qm0 + r) * HQ + h) * DHD + c * 32 + x * 8);
    }
    flash_load_k(kRing[0], tid, 0, hk, Kh, Kl);
    cp_commit();
    flash_load_v(vRing[0], tid, 0, hk, Vth, Vtl);
    cp_commit();

    uint32_t qfh[8][4], qfl[8][4];
    float oacc[16][4];
#pragma unroll
    for (int jj = 0; jj < 16; jj++)
#pragma unroll
        for (int x = 0; x < 4; x++) oacc[jj][x] = 0.f;
    float m0 = -1e30f, m1 = -1e30f, l0 = 0.f, l1 = 0.f;

    for (int t = 0; t <= qt; t++) {
        const uint32_t kb = kRing[t % 3];
        const uint32_t vb = vRing[t % 3];

        cp_wait<1>();           // K_t (and Q at t=0) complete
        __syncthreads();

        if (t == 0) {
#pragma unroll
            for (int kk = 0; kk < 8; kk++) {
                int c = kk >> 1, x = (kk & 1) * 2 + lc;
                ldsm_x4(qfh[kk], swz(qBase + c * 4096, wBase + lr, x));
                ldsm_x4(qfl[kk], swz(qBase + 16384 + c * 4096, wBase + lr, x));
            }
        }

        // prefetch K_{t+1} BEFORE the S phase so the load overlaps all S mma.
        if (t < qt) {
            flash_load_k(kRing[(t + 1) % 3], tid, (t + 1) * FBN, hk, Kh, Kl);
            cp_commit();
        }

        float sacc[8][4];
#pragma unroll
        for (int j = 0; j < 8; j++)
#pragma unroll
            for (int x = 0; x < 4; x++) sacc[j][x] = 0.f;

#pragma unroll
        for (int kk = 0; kk < 8; kk++) {
            int c = kk >> 1, x = (kk & 1) * 2 + lc;
            uint32_t kbf[4][4];
#pragma unroll
            for (int g = 0; g < 4; g++)
                ldsm_x4(kbf[g], swz(kb + c * 4096, g * 16 + lr, x));
#pragma unroll
            for (int j = 0; j < 8; j++) {
                uint32_t bf[2] = {kbf[j >> 1][j & 1], kbf[j >> 1][(j & 1) + 2]};
                mma_bf16(sacc[j], qfh[kk], bf, sacc[j]);
            }
#pragma unroll
            for (int j = 0; j < 8; j++) {
                uint32_t bf[2] = {kbf[j >> 1][j & 1], kbf[j >> 1][(j & 1) + 2]};
                mma_bf16(sacc[j], qfl[kk], bf, sacc[j]);
            }
#pragma unroll
            for (int g = 0; g < 4; g++)
                ldsm_x4(kbf[g], swz(kb + 16384 + c * 4096, g * 16 + lr, x));
#pragma unroll
            for (int j = 0; j < 8; j++) {
                uint32_t bf[2] = {kbf[j >> 1][j & 1], kbf[j >> 1][(j & 1) + 2]};
                mma_bf16(sacc[j], qfh[kk], bf, sacc[j]);
            }
        }

        if (t == qt) {
            int row0 = qm0 + wBase + erow, row1 = row0 + 8;
            int colb = t * FBN + q4 * 2;
#pragma unroll
            for (int j = 0; j < 8; j++) {
                int c0 = colb + j * 8, c1 = c0 + 1;
                if (c0 > row0) sacc[j][0] = -1e30f;
                if (c1 > row0) sacc[j][1] = -1e30f;
                if (c0 > row1) sacc[j][2] = -1e30f;
                if (c1 > row1) sacc[j][3] = -1e30f;
            }
        }

        float mx0 = -1e30f, mx1 = -1e30f;
#pragma unroll
        for (int j = 0; j < 8; j++) {
            mx0 = fmaxf(mx0, fmaxf(sacc[j][0], sacc[j][1]));
            mx1 = fmaxf(mx1, fmaxf(sacc[j][2], sacc[j][3]));
        }
        mx0 = fmaxf(mx0, __shfl_xor_sync(0xFFFFFFFFu, mx0, 1));
        mx0 = fmaxf(mx0, __shfl_xor_sync(0xFFFFFFFFu, mx0, 2));
        mx1 = fmaxf(mx1, __shfl_xor_sync(0xFFFFFFFFu, mx1, 1));
        mx1 = fmaxf(mx1, __shfl_xor_sync(0xFFFFFFFFu, mx1, 2));
        float mn0 = fmaxf(m0, mx0), mn1 = fmaxf(m1, mx1);
        float a0 = __expf(m0 - mn0), a1 = __expf(m1 - mn1);
        float s0 = 0.f, s1 = 0.f;
#pragma unroll
        for (int j = 0; j < 8; j++) {
            float p0 = __expf(sacc[j][0] - mn0); sacc[j][0] = p0; s0 += p0;
            float p1 = __expf(sacc[j][1] - mn0); sacc[j][1] = p1; s0 += p1;
            float p2 = __expf(sacc[j][2] - mn1); sacc[j][2] = p2; s1 += p2;
            float p3 = __expf(sacc[j][3] - mn1); sacc[j][3] = p3; s1 += p3;
        }
        s0 += __shfl_xor_sync(0xFFFFFFFFu, s0, 1);
        s0 += __shfl_xor_sync(0xFFFFFFFFu, s0, 2);
        s1 += __shfl_xor_sync(0xFFFFFFFFu, s1, 1);
        s1 += __shfl_xor_sync(0xFFFFFFFFu, s1, 2);
        l0 = l0 * a0 + s0;
        l1 = l1 * a1 + s1;
        m0 = mn0; m1 = mn1;
#pragma unroll
        for (int jj = 0; jj < 16; jj++) {
            oacc[jj][0] *= a0; oacc[jj][1] *= a0;
            oacc[jj][2] *= a1; oacc[jj][3] *= a1;
        }

        if (t < qt) cp_wait<1>(); else cp_wait<0>();
        __syncthreads();

        if (t < qt) {
            flash_load_v(vRing[(t + 1) % 3], tid, (t + 1) * FBN, hk, Vth, Vtl);
            cp_commit();
        }

#pragma unroll
        for (int tt = 0; tt < 4; tt++) {
            uint32_t ph[4], pl[4];
            {
                __nv_bfloat162 v0 = __floats2bfloat162_rn(sacc[2*tt][0],   sacc[2*tt][1]);
                __nv_bfloat162 v1 = __floats2bfloat162_rn(sacc[2*tt][2],   sacc[2*tt][3]);
                __nv_bfloat162 v2 = __floats2bfloat162_rn(sacc[2*tt+1][0], sacc[2*tt+1][1]);
                __nv_bfloat162 v3 = __floats2bfloat162_rn(sacc[2*tt+1][2], sacc[2*tt+1][3]);
                ph[0] = *(uint32_t*)&v0; ph[1] = *(uint32_t*)&v1;
                ph[2] = *(uint32_t*)&v2; ph[3] = *(uint32_t*)&v3;
                __nv_bfloat162 w0 = __floats2bfloat162_rn(
                    sacc[2*tt][0]   - __bfloat162float(v0.x), sacc[2*tt][1]   - __bfloat162float(v0.y));
                __nv_bfloat162 w1 = __floats2bfloat162_rn(
                    sacc[2*tt][2]   - __bfloat162float(v1.x), sacc[2*tt][3]   - __bfloat162float(v1.y));
                __nv_bfloat162 w2 = __floats2bfloat162_rn(
                    sacc[2*tt+1][0] - __bfloat162float(v2.x), sacc[2*tt+1][1] - __bfloat162float(v2.y));
                __nv_bfloat162 w3 = __floats2bfloat162_rn(
                    sacc[2*tt+1][2] - __bfloat162float(v3.x), sacc[2*tt+1][3] - __bfloat162float(v3.y));
                pl[0] = *(uint32_t*)&w0; pl[1] = *(uint32_t*)&w1;
                pl[2] = *(uint32_t*)&w2; pl[3] = *(uint32_t*)&w3;
            }
            int kc = tt >> 1, x = (tt & 1) * 2 + lc;
            uint32_t vbf[8][4];
#pragma unroll
            for (int g = 0; g < 8; g++)
                ldsm_x4(vbf[g], swz(vb + kc * 8192, g * 16 + lr, x));
#pragma unroll
            for (int jj = 0; jj < 16; jj++) {
                uint32_t bf[2] = {vbf[jj >> 1][jj & 1], vbf[jj >> 1][(jj & 1) + 2]};
                mma_bf16(oacc[jj], ph, bf, oacc[jj]);
            }
#pragma unroll
            for (int jj = 0; jj < 16; jj++) {
                uint32_t bf[2] = {vbf[jj >> 1][jj & 1], vbf[jj >> 1][(jj & 1) + 2]};
                mma_bf16(oacc[jj], pl, bf, oacc[jj]);
            }
#pragma unroll
            for (int g = 0; g < 8; g++)
                ldsm_x4(vbf[g], swz(vb + 16384 + kc * 8192, g * 16 + lr, x));
#pragma unroll
            for (int jj = 0; jj < 16; jj++) {
                uint32_t bf[2] = {vbf[jj >> 1][jj & 1], vbf[jj >> 1][(jj & 1) + 2]};
                mma_bf16(oacc[jj], ph, bf, oacc[jj]);
            }
        }
    }

    float il0 = 1.0f / l0, il1 = 1.0f / l1;
    int row0 = qm0 + wBase + erow;
#pragma unroll
    for (int jj = 0; jj < 16; jj++) {
        int col = jj * 8 + q4 * 2;
        {
            float o0 = oacc[jj][0] * il0, o1 = oacc[jj][1] * il0;
            __nv_bfloat162 hh = __floats2bfloat162_rn(o0, o1);
            __nv_bfloat162 ll = __floats2bfloat162_rn(o0 - __bfloat162float(hh.x),
                                                      o1 - __bfloat162float(hh.y));
            size_t off = (size_t)row0 * QSTR + h * DHD + col;
            *(__nv_bfloat162*)(Oh + off) = hh;
            *(__nv_bfloat162*)(Ol + off) = ll;
        }
        {
            float o0 = oacc[jj][2] * il1, o1 = oacc[jj][3] * il1;
            __nv_bfloat162 hh = __floats2bfloat162_rn(o0, o1);
            __nv_bfloat162 ll = __floats2bfloat162_rn(o0 - __bfloat162float(hh.x),
                                                      o1 - __bfloat162float(hh.y));
            size_t off = (size_t)(row0 + 8) * QSTR + h * DHD + col;
            *(__nv_bfloat162*)(Oh + off) = hh;
            *(__nv_bfloat162*)(Ol + off) = ll;
        }
    }
}

// ------------------------- launch -----------------------------------------------
extern "C" void kernel_launch(void* const* d_in, const int* in_sizes, int n_in,
                              void* d_out, int out_size)
{
    (void)in_sizes; (void)n_in; (void)out_size;
    const float* hs   = (const float*)d_in[0];
    const float* cosp = (const float*)d_in[1];
    const float* sinp = (const float*)d_in[2];
    const float* wq   = (const float*)d_in[3];
    const float* wk   = (const float*)d_in[4];
    const float* wv   = (const float*)d_in[5];
    const float* wo   = (const float*)d_in[6];
    const float* qnw  = (const float*)d_in[7];
    const float* knw  = (const float*)d_in[8];
    float* out = (float*)d_out;

    float *qp, *kp, *vp;
    cudaGetSymbolAddress((void**)&qp, g_q);
    cudaGetSymbolAddress((void**)&kp, g_k);
    cudaGetSymbolAddress((void**)&vp, g_v);
    __nv_bfloat16 *hsh, *hsl, *ath, *atl;
    __nv_bfloat16 *qh, *ql, *kh, *kl, *vth, *vtl;
    __nv_bfloat16 *wqh, *wql, *wkh, *wkl, *wvh, *wvl, *woh, *wol;
    cudaGetSymbolAddress((void**)&hsh, g_hs_h);
    cudaGetSymbolAddress((void**)&hsl, g_hs_l);
    cudaGetSymbolAddress((void**)&ath, g_at_h);
    cudaGetSymbolAddress((void**)&atl, g_at_l);
    cudaGetSymbolAddress((void**)&qh, g_qh);
    cudaGetSymbolAddress((void**)&ql, g_ql);
    cudaGetSymbolAddress((void**)&kh, g_kh);
    cudaGetSymbolAddress((void**)&kl, g_kl);
    cudaGetSymbolAddress((void**)&vth, g_vth);
    cudaGetSymbolAddress((void**)&vtl, g_vtl);
    cudaGetSymbolAddress((void**)&wqh, g_wq_h);
    cudaGetSymbolAddress((void**)&wql, g_wq_l);
    cudaGetSymbolAddress((void**)&wkh, g_wk_h);
    cudaGetSymbolAddress((void**)&wkl, g_wk_l);
    cudaGetSymbolAddress((void**)&wvh, g_wv_h);
    cudaGetSymbolAddress((void**)&wvl, g_wv_l);
    cudaGetSymbolAddress((void**)&woh, g_wo_h);
    cudaGetSymbolAddress((void**)&wol, g_wo_l);

    cudaFuncSetAttribute(gemm_qkv, cudaFuncAttributeMaxDynamicSharedMemorySize, G_SMEM);
    cudaFuncSetAttribute(gemm_bf16x3, cudaFuncAttributeMaxDynamicSharedMemorySize, G_SMEM);
    cudaFuncSetAttribute(flash_hmma, cudaFuncAttributeMaxDynamicSharedMemorySize, F_SMEM);

    // 1) input prep: hs split + all weight transposes (one launch)
    prep_inputs<<<18432, 256>>>(hs, wq, wk, wv, wo, hsh, hsl,
                                wqh, wql, wkh, wkl, wvh, wvl, woh, wol);
    // 2) fused QKV projection
    gemm_qkv<<<dim3(48, S_LEN / 128), 256, G_SMEM>>>(
        hsh, hsl, wqh, wql, wkh, wkl, wvh, wvl, qp, kp, vp);
    // 3) attention prep: rms+rope Q, rms+rope K, V transpose (one launch)
    prep_attn<<<12288, 256>>>(qp, kp, vp, cosp, sinp, qnw, knw,
                              qh, ql, kh, kl, vth, vtl);
    // 4) causal flash attention  (lands in the ncu capture window)
    flash_hmma<<<dim3(S_LEN / FBM, HQ), 128, F_SMEM>>>(
        qh, ql, kh, kl, vth, vtl, ath, atl);
    // 5) output projection
    gemm_bf16x3<<<dim3(HIDDEN / 64, S_LEN / 128), 256, G_SMEM>>>(
        ath, atl, woh, wol, out, S_LEN, HIDDEN, QSTR);
}

// round 10
// speedup vs baseline: 1.2933x; 1.2900x over previous
#include <cuda_runtime.h>
#include <cuda_bf16.h>
#include <cuda_fp16.h>
#include <math.h>
#include <stdint.h>

#define S_LEN 4096
#define HIDDEN 2048
#define HQ 16
#define HKV 4
#define DHD 128
#define QSTR (HQ*DHD)    // 2048
#define KSTR (HKV*DHD)   // 512
#define RMS_EPS 1e-6f
#define SM_SCALE 0.08838834764831845f  // 128^-0.5

// ------------------------- scratch (static device globals) ----------------------
__device__ float g_q[S_LEN * QSTR];
__device__ float g_k[S_LEN * KSTR];
__device__ float g_v[S_LEN * KSTR];

__device__ __nv_bfloat16 g_hs_h[S_LEN * HIDDEN];
__device__ __nv_bfloat16 g_hs_l[S_LEN * HIDDEN];
__device__ __nv_bfloat16 g_at_h[S_LEN * QSTR];
__device__ __nv_bfloat16 g_at_l[S_LEN * QSTR];
// flash operands: single fp16 (q, k, v^T)
__device__ __half g_qh[S_LEN * QSTR];
__device__ __half g_kh[S_LEN * KSTR];
__device__ __half g_vth[KSTR * S_LEN];   // [hk*128+d][s]
// transposed weights [N, K] bf16 hi/lo
__device__ __nv_bfloat16 g_wq_h[QSTR * HIDDEN];
__device__ __nv_bfloat16 g_wq_l[QSTR * HIDDEN];
__device__ __nv_bfloat16 g_wk_h[KSTR * HIDDEN];
__device__ __nv_bfloat16 g_wk_l[KSTR * HIDDEN];
__device__ __nv_bfloat16 g_wv_h[KSTR * HIDDEN];
__device__ __nv_bfloat16 g_wv_l[KSTR * HIDDEN];
__device__ __nv_bfloat16 g_wo_h[HIDDEN * QSTR];
__device__ __nv_bfloat16 g_wo_l[HIDDEN * QSTR];

// ------------------------- helpers ----------------------------------------------
__device__ __forceinline__ uint32_t smem_u32(const void* p) {
    uint32_t a;
    asm("{ .reg .u64 t; cvta.to.shared.u64 t, %1; cvt.u32.u64 %0, t; }" : "=r"(a) : "l"(p));
    return a;
}
__device__ __forceinline__ void ldsm_x4(uint32_t* r, uint32_t addr) {
    asm volatile("ldmatrix.sync.aligned.m8n8.x4.shared.b16 {%0,%1,%2,%3}, [%4];"
                 : "=r"(r[0]), "=r"(r[1]), "=r"(r[2]), "=r"(r[3]) : "r"(addr));
}
__device__ __forceinline__ void mma_bf16(float* d, const uint32_t* a, const uint32_t* b,
                                         const float* c) {
    asm volatile(
        "mma.sync.aligned.m16n8k16.row.col.f32.bf16.bf16.f32 "
        "{%0,%1,%2,%3}, {%4,%5,%6,%7}, {%8,%9}, {%10,%11,%12,%13};"
        : "=f"(d[0]), "=f"(d[1]), "=f"(d[2]), "=f"(d[3])
        : "r"(a[0]), "r"(a[1]), "r"(a[2]), "r"(a[3]),
          "r"(b[0]), "r"(b[1]),
          "f"(c[0]), "f"(c[1]), "f"(c[2]), "f"(c[3]));
}
__device__ __forceinline__ void mma_f16(float* d, const uint32_t* a, const uint32_t* b,
                                        const float* c) {
    asm volatile(
        "mma.sync.aligned.m16n8k16.row.col.f32.f16.f16.f32 "
        "{%0,%1,%2,%3}, {%4,%5,%6,%7}, {%8,%9}, {%10,%11,%12,%13};"
        : "=f"(d[0]), "=f"(d[1]), "=f"(d[2]), "=f"(d[3])
        : "r"(a[0]), "r"(a[1]), "r"(a[2]), "r"(a[3]),
          "r"(b[0]), "r"(b[1]),
          "f"(c[0]), "f"(c[1]), "f"(c[2]), "f"(c[3]));
}
__device__ __forceinline__ void cp_async16(uint32_t dst, const void* src) {
    asm volatile("cp.async.cg.shared.global [%0], [%1], 16;" :: "r"(dst), "l"(src) : "memory");
}
__device__ __forceinline__ void cp_commit() {
    asm volatile("cp.async.commit_group;" ::: "memory");
}
template<int N> __device__ __forceinline__ void cp_wait() {
    asm volatile("cp.async.wait_group %0;" :: "n"(N) : "memory");
}
// logical tile rows of 64B (32 b16 elems) with XOR swizzle
__device__ __forceinline__ uint32_t swz(uint32_t tileBase, int r, int c) {
    uint32_t off = r * 64 + c * 16;
    off ^= ((off >> 7) & 7) << 4;
    return tileBase + off;
}

// ------------------------- transpose+split device cores --------------------------
__device__ __forceinline__ void wt_tile(
    const float* __restrict__ W, __nv_bfloat16* __restrict__ Th,
    __nv_bfloat16* __restrict__ Tl, int K, int N, int n0, int k0)
{
    __shared__ float t[32][33];
    int tx = threadIdx.x & 31, ty = threadIdx.x >> 5;
#pragma unroll
    for (int j = 0; j < 4; j++)
        t[ty + 8 * j][tx] = W[(size_t)(k0 + ty + 8 * j) * N + n0 + tx];
    __syncthreads();
#pragma unroll
    for (int j = 0; j < 4; j++) {
        float v = t[tx][ty + 8 * j];
        __nv_bfloat16 h = __float2bfloat16(v);
        size_t o = (size_t)(n0 + ty + 8 * j) * K + k0 + tx;
        Th[o] = h;
        Tl[o] = __float2bfloat16(v - __bfloat162float(h));
    }
}
// single-fp16 transpose (for V^T)
__device__ __forceinline__ void wt_tile_h(
    const float* __restrict__ W, __half* __restrict__ Th,
    int K, int N, int n0, int k0)
{
    __shared__ float t[32][33];
    int tx = threadIdx.x & 31, ty = threadIdx.x >> 5;
#pragma unroll
    for (int j = 0; j < 4; j++)
        t[ty + 8 * j][tx] = W[(size_t)(k0 + ty + 8 * j) * N + n0 + tx];
    __syncthreads();
#pragma unroll
    for (int j = 0; j < 4; j++) {
        size_t o = (size_t)(n0 + ty + 8 * j) * K + k0 + tx;
        Th[o] = __float2half(t[tx][ty + 8 * j]);
    }
}

// merged input prep: hs split (8192 blocks) + all 4 weight transposes (10240)
__global__ __launch_bounds__(256) void prep_inputs(
    const float* __restrict__ hs,
    const float* __restrict__ wq, const float* __restrict__ wk,
    const float* __restrict__ wv, const float* __restrict__ wo,
    __nv_bfloat16* __restrict__ hsh, __nv_bfloat16* __restrict__ hsl,
    __nv_bfloat16* __restrict__ wqh, __nv_bfloat16* __restrict__ wql,
    __nv_bfloat16* __restrict__ wkh, __nv_bfloat16* __restrict__ wkl,
    __nv_bfloat16* __restrict__ wvh, __nv_bfloat16* __restrict__ wvl,
    __nv_bfloat16* __restrict__ woh, __nv_bfloat16* __restrict__ wol)
{
    int b = blockIdx.x;
    if (b < 8192) {
        int i = (b * 256 + threadIdx.x) * 4;
        float4 v = *(const float4*)(hs + i);
        __nv_bfloat16 h0 = __float2bfloat16(v.x), h1 = __float2bfloat16(v.y);
        __nv_bfloat16 h2 = __float2bfloat16(v.z), h3 = __float2bfloat16(v.w);
        __nv_bfloat16 l0 = __float2bfloat16(v.x - __bfloat162float(h0));
        __nv_bfloat16 l1 = __float2bfloat16(v.y - __bfloat162float(h1));
        __nv_bfloat16 l2 = __float2bfloat16(v.z - __bfloat162float(h2));
        __nv_bfloat16 l3 = __float2bfloat16(v.w - __bfloat162float(h3));
        *(__nv_bfloat162*)(hsh + i)     = __halves2bfloat162(h0, h1);
        *(__nv_bfloat162*)(hsh + i + 2) = __halves2bfloat162(h2, h3);
        *(__nv_bfloat162*)(hsl + i)     = __halves2bfloat162(l0, l1);
        *(__nv_bfloat162*)(hsl + i + 2) = __halves2bfloat162(l2, l3);
        return;
    }
    b -= 8192;
    if (b < 4096)
        wt_tile(wq, wqh, wql, HIDDEN, QSTR, (b & 63) * 32, (b >> 6) * 32);
    else if (b < 5120) {
        int l = b - 4096;
        wt_tile(wk, wkh, wkl, HIDDEN, KSTR, (l & 15) * 32, (l >> 4) * 32);
    } else if (b < 6144) {
        int l = b - 5120;
        wt_tile(wv, wvh, wvl, HIDDEN, KSTR, (l & 15) * 32, (l >> 4) * 32);
    } else {
        int l = b - 6144;
        wt_tile(wo, woh, wol, QSTR, HIDDEN, (l & 63) * 32, (l >> 6) * 32);
    }
}

// ------------------------- bf16x3 HMMA GEMM core (K-chunk 64) --------------------
#define GA_SUB 8192
#define GB_SUB 4096
#define GSTAGE 49152
#define G_SMEM (2 * GSTAGE)

__device__ __forceinline__ void gemm_stage(
    uint32_t st, int k0, int tid, int K,
    const __nv_bfloat16* __restrict__ A0h, const __nv_bfloat16* __restrict__ A0l,
    const __nv_bfloat16* __restrict__ B0h, const __nv_bfloat16* __restrict__ B0l)
{
#pragma unroll
    for (int s2 = 0; s2 < 12; s2++) {
        int i = tid + 256 * s2;
        if (i < 2048) {
            int idx = i >> 9;
            int r = (i >> 2) & 127, x = i & 3;
            const __nv_bfloat16* base = (idx >> 1) ? A0l : A0h;
            cp_async16(swz(st + idx * GA_SUB, r, x),
                       base + (size_t)r * K + k0 + (idx & 1) * 32 + x * 8);
        } else {
            int j = i - 2048;
            int idx = j >> 8;
            int r = (j >> 2) & 63, x = j & 3;
            const __nv_bfloat16* base = (idx >> 1) ? B0l : B0h;
            cp_async16(swz(st + 4 * GA_SUB + idx * GB_SUB, r, x),
                       base + (size_t)r * K + k0 + (idx & 1) * 32 + x * 8);
        }
    }
    cp_commit();
}

__device__ __forceinline__ void gemm_core(
    const __nv_bfloat16* __restrict__ A0h, const __nv_bfloat16* __restrict__ A0l,
    const __nv_bfloat16* __restrict__ B0h, const __nv_bfloat16* __restrict__ B0l,
    float* __restrict__ C0, int ldc, int K, uint32_t sb)
{
    const int tid  = threadIdx.x;
    const int wid  = tid >> 5;
    const int lane = tid & 31;
    const int mBase = (wid >> 1) * 32;
    const int nBase = (wid & 1) * 32;
    const int lr = lane & 15, lc = lane >> 4;

    float acc[2][4][4];
#pragma unroll
    for (int f = 0; f < 2; f++)
#pragma unroll
        for (int j = 0; j < 4; j++)
#pragma unroll
            for (int x = 0; x < 4; x++) acc[f][j][x] = 0.f;

    const int nChunks = K >> 6;
    gemm_stage(sb, 0, tid, K, A0h, A0l, B0h, B0l);

    for (int kc = 0; kc < nChunks; kc++) {
        const uint32_t st = sb + (kc & 1) * GSTAGE;
        if (kc + 1 < nChunks) {
            gemm_stage(sb + ((kc + 1) & 1) * GSTAGE, (kc + 1) << 6, tid, K,
                       A0h, A0l, B0h, B0l);
            cp_wait<1>();
        } else {
            cp_wait<0>();
        }
        __syncthreads();

#pragma unroll
        for (int s16 = 0; s16 < 4; s16++) {
            const int sub = s16 >> 1;
            const int ch  = (s16 & 1) * 2 + lc;
            const uint32_t tAh = st + sub * GA_SUB;
            const uint32_t tAl = st + 2 * GA_SUB + sub * GA_SUB;
            const uint32_t tBh = st + 4 * GA_SUB + sub * GB_SUB;
            const uint32_t tBl = st + 4 * GA_SUB + 2 * GB_SUB + sub * GB_SUB;

            uint32_t ah[2][4], al[2][4], bb[2][4];
#pragma unroll
            for (int f = 0; f < 2; f++)
                ldsm_x4(ah[f], swz(tAh, mBase + f * 16 + lr, ch));
#pragma unroll
            for (int g = 0; g < 2; g++)
                ldsm_x4(bb[g], swz(tBh, nBase + g * 16 + lr, ch));
#pragma unroll
            for (int f = 0; f < 2; f++)
#pragma unroll
                for (int j = 0; j < 4; j++) {
                    uint32_t bfr[2] = {bb[j >> 1][j & 1], bb[j >> 1][2 + (j & 1)]};
                    mma_bf16(acc[f][j], ah[f], bfr, acc[f][j]);
                }
#pragma unroll
            for (int f = 0; f < 2; f++)
                ldsm_x4(al[f], swz(tAl, mBase + f * 16 + lr, ch));
#pragma unroll
            for (int f = 0; f < 2; f++)
#pragma unroll
                for (int j = 0; j < 4; j++) {
                    uint32_t bfr[2] = {bb[j >> 1][j & 1], bb[j >> 1][2 + (j & 1)]};
                    mma_bf16(acc[f][j], al[f], bfr, acc[f][j]);
                }
#pragma unroll
            for (int g = 0; g < 2; g++)
                ldsm_x4(bb[g], swz(tBl, nBase + g * 16 + lr, ch));
#pragma unroll
            for (int f = 0; f < 2; f++)
#pragma unroll
                for (int j = 0; j < 4; j++) {
                    uint32_t bfr[2] = {bb[j >> 1][j & 1], bb[j >> 1][2 + (j & 1)]};
                    mma_bf16(acc[f][j], ah[f], bfr, acc[f][j]);
                }
        }
        __syncthreads();
    }

    const int erow = lane >> 2;
    const int ecol = (lane & 3) * 2;
#pragma unroll
    for (int f = 0; f < 2; f++) {
        int rl = mBase + f * 16 + erow;
#pragma unroll
        for (int j = 0; j < 4; j++) {
            int cl = nBase + j * 8 + ecol;
            *(float2*)(C0 + (size_t)rl * ldc + cl)       = make_float2(acc[f][j][0], acc[f][j][1]);
            *(float2*)(C0 + (size_t)(rl + 8) * ldc + cl) = make_float2(acc[f][j][2], acc[f][j][3]);
        }
    }
}

__global__ __launch_bounds__(256, 2) void gemm_qkv(
    const __nv_bfloat16* __restrict__ Ah, const __nv_bfloat16* __restrict__ Al,
    const __nv_bfloat16* __restrict__ wqh, const __nv_bfloat16* __restrict__ wql,
    const __nv_bfloat16* __restrict__ wkh, const __nv_bfloat16* __restrict__ wkl,
    const __nv_bfloat16* __restrict__ wvh, const __nv_bfloat16* __restrict__ wvl,
    float* __restrict__ Q, float* __restrict__ K, float* __restrict__ V)
{
    extern __shared__ char smc[];
    const uint32_t sb = smem_u32(smc);
    const int bx = blockIdx.x;
    const int m0 = blockIdx.y * 128;

    const __nv_bfloat16 *Bh, *Bl;
    float* C;
    int n0, ldc;
    if (bx < 32)      { Bh = wqh; Bl = wql; C = Q; n0 = bx * 64;        ldc = QSTR; }
    else if (bx < 40) { Bh = wkh; Bl = wkl; C = K; n0 = (bx - 32) * 64; ldc = KSTR; }
    else              { Bh = wvh; Bl = wvl; C = V; n0 = (bx - 40) * 64; ldc = KSTR; }

    gemm_core(Ah + (size_t)m0 * HIDDEN, Al + (size_t)m0 * HIDDEN,
              Bh + (size_t)n0 * HIDDEN, Bl + (size_t)n0 * HIDDEN,
              C + (size_t)m0 * ldc + n0, ldc, HIDDEN, sb);
}

__global__ __launch_bounds__(256, 2) void gemm_bf16x3(
    const __nv_bfloat16* __restrict__ Ah, const __nv_bfloat16* __restrict__ Al,
    const __nv_bfloat16* __restrict__ Bh, const __nv_bfloat16* __restrict__ Bl,
    float* __restrict__ C, int M, int N, int K)
{
    extern __shared__ char smc[];
    const uint32_t sb = smem_u32(smc);
    const int m0 = blockIdx.y * 128, n0 = blockIdx.x * 64;
    gemm_core(Ah + (size_t)m0 * K, Al + (size_t)m0 * K,
              Bh + (size_t)n0 * K, Bl + (size_t)n0 * K,
              C + (size_t)m0 * N + n0, N, K, sb);
}

// ------------------------- fused attention prep (one launch) ---------------------
// Q/K rows -> rmsnorm + rope -> single fp16.  V -> transposed single fp16.
__device__ __forceinline__ void rms_rope_rows_h(
    const float* __restrict__ in, const float* __restrict__ cosp,
    const float* __restrict__ sinp, const float* __restrict__ w,
    int nh, float outScale, int rowBase, __half* __restrict__ H)
{
    const int lane = threadIdx.x & 31;
    const int rowIdx = rowBase + (threadIdx.x >> 5);
    const int s = rowIdx / nh;
    const int d0 = lane * 2;

    const float* x = in + (size_t)rowIdx * DHD;
    float2 a = *(const float2*)(x + d0);
    float2 b = *(const float2*)(x + 64 + d0);

    float ss = a.x * a.x + a.y * a.y + b.x * b.x + b.y * b.y;
#pragma unroll
    for (int o = 16; o > 0; o >>= 1) ss += __shfl_xor_sync(0xFFFFFFFFu, ss, o);
    float inv = rsqrtf(ss * (1.0f / DHD) + RMS_EPS);

    float2 wa = *(const float2*)(w + d0);
    float2 wb = *(const float2*)(w + 64 + d0);
    const float* cs = cosp + (size_t)s * DHD;
    const float* sn = sinp + (size_t)s * DHD;
    float2 ca = *(const float2*)(cs + d0), cb = *(const float2*)(cs + 64 + d0);
    float2 sa = *(const float2*)(sn + d0), sb2 = *(const float2*)(sn + 64 + d0);

    float xa0 = a.x * inv * wa.x, xa1 = a.y * inv * wa.y;
    float xb0 = b.x * inv * wb.x, xb1 = b.y * inv * wb.y;
    float oa0 = (xa0 * ca.x - xb0 * sa.x) * outScale;
    float oa1 = (xa1 * ca.y - xb1 * sa.y) * outScale;
    float ob0 = (xb0 * cb.x + xa0 * sb2.x) * outScale;
    float ob1 = (xb1 * cb.y + xa1 * sb2.y) * outScale;

    size_t off = (size_t)rowIdx * DHD + d0;
    *(__half2*)(H + off)      = __floats2half2_rn(oa0, oa1);
    *(__half2*)(H + off + 64) = __floats2half2_rn(ob0, ob1);
}

__global__ __launch_bounds__(256) void prep_attn(
    const float* __restrict__ qp, const float* __restrict__ kp,
    const float* __restrict__ vp,
    const float* __restrict__ cosp, const float* __restrict__ sinp,
    const float* __restrict__ qnw, const float* __restrict__ knw,
    __half* __restrict__ qh, __half* __restrict__ kh,
    __half* __restrict__ vth)
{
    int b = blockIdx.x;
    if (b < 8192)
        rms_rope_rows_h(qp, cosp, sinp, qnw, HQ, SM_SCALE, b * 8, qh);
    else if (b < 10240)
        rms_rope_rows_h(kp, cosp, sinp, knw, HKV, 1.0f, (b - 8192) * 8, kh);
    else {
        int l = b - 10240;   // vT: 16 x 128 tiles of 32x32
        wt_tile_h(vp, vth, S_LEN, KSTR, (l & 15) * 32, (l >> 4) * 32);
    }
}

// ------------------------- fp16 HMMA causal flash attention ----------------------
// CTA: 64 queries x 1 head, 4 warps. Q/K single fp16 (1-pass S), P split + V
// single fp16 (2-pass PV). K and V double-buffered 16 KB slots; Q staged once.
#define FBM 64
#define FBN 64
#define FQ_OFF 0
#define FK_OFF(i) (16384 + (i) * 16384)
#define FV_OFF(i) (49152 + (i) * 16384)
#define F_SMEM 81920

__device__ __forceinline__ void flash_load_k(
    uint32_t dst, int tid, int kg0, int hk, const __half* Kh)
{
#pragma unroll
    for (int s = 0; s < 8; s++) {
        int i = tid + 128 * s;
        int c = i >> 8, r = (i >> 2) & 63, x = i & 3;
        cp_async16(swz(dst + c * 4096, r, x),
                   Kh + ((size_t)(kg0 + r) * HKV + hk) * DHD + c * 32 + x * 8);
    }
}
__device__ __forceinline__ void flash_load_v(
    uint32_t dst, int tid, int kg0, int hk, const __half* Vth)
{
#pragma unroll
    for (int s = 0; s < 8; s++) {
        int i = tid + 128 * s;
        int kc = i >> 9, r = (i >> 2) & 127, x = i & 3;
        cp_async16(swz(dst + kc * 8192, r, x),
                   Vth + (size_t)(hk * DHD + r) * S_LEN + kg0 + kc * 32 + x * 8);
    }
}

__global__ __launch_bounds__(128, 2) void flash_hmma(
    const __half* __restrict__ Qh, const __half* __restrict__ Kh,
    const __half* __restrict__ Vth,
    __nv_bfloat16* __restrict__ Oh, __nv_bfloat16* __restrict__ Ol)
{
    extern __shared__ char smf[];
    const uint32_t sb = smem_u32(smf);
    const int tid = threadIdx.x, wid = tid >> 5, lane = tid & 31;
    const int qt = (int)gridDim.x - 1 - (int)blockIdx.x;   // heavy tiles first
    const int h = blockIdx.y, hk = h >> 2;
    const int qm0 = qt * FBM;
    const int wBase = wid * 16;
    const int lr = lane & 15, lc = lane >> 4;
    const int erow = lane >> 2, q4 = lane & 3;

    // prologue: Q + K0 in group A, V0 in group B
#pragma unroll
    for (int s = 0; s < 8; s++) {
        int i = tid + 128 * s;
        int c = i >> 8, r = (i >> 2) & 63, x = i & 3;
        cp_async16(swz(sb + FQ_OFF + c * 4096, r, x),
                   Qh + ((size_t)(qm0 + r) * HQ + h) * DHD + c * 32 + x * 8);
    }
    flash_load_k(sb + FK_OFF(0), tid, 0, hk, Kh);
    cp_commit();
    flash_load_v(sb + FV_OFF(0), tid, 0, hk, Vth);
    cp_commit();

    uint32_t qf[8][4];
    float oacc[16][4];
#pragma unroll
    for (int jj = 0; jj < 16; jj++)
#pragma unroll
        for (int x = 0; x < 4; x++) oacc[jj][x] = 0.f;
    float m0 = -1e30f, m1 = -1e30f, l0 = 0.f, l1 = 0.f;

    for (int t = 0; t <= qt; t++) {
        const uint32_t kb = sb + FK_OFF(t & 1);
        const uint32_t vb = sb + FV_OFF(t & 1);

        cp_wait<1>();           // K_t (and Q at t=0) complete; V_t may be pending
        __syncthreads();

        if (t == 0) {
#pragma unroll
            for (int kk = 0; kk < 8; kk++) {
                int c = kk >> 1, x = (kk & 1) * 2 + lc;
                ldsm_x4(qf[kk], swz(sb + FQ_OFF + c * 4096, wBase + lr, x));
            }
        }

        // prefetch K_{t+1} (slot held K_{t-1}, fully consumed)
        if (t < qt) {
            flash_load_k(sb + FK_OFF((t + 1) & 1), tid, (t + 1) * FBN, hk, Kh);
            cp_commit();
        }

        // ---- S = Q @ K^T, single fp16 pass
        float sacc[8][4];
#pragma unroll
        for (int j = 0; j < 8; j++)
#pragma unroll
            for (int x = 0; x < 4; x++) sacc[j][x] = 0.f;

#pragma unroll
        for (int kk = 0; kk < 8; kk++) {
            int c = kk >> 1, x = (kk & 1) * 2 + lc;
            uint32_t kbf[4][4];
#pragma unroll
            for (int g = 0; g < 4; g++)
                ldsm_x4(kbf[g], swz(kb + c * 4096, g * 16 + lr, x));
#pragma unroll
            for (int j = 0; j < 8; j++) {
                uint32_t bf[2] = {kbf[j >> 1][j & 1], kbf[j >> 1][(j & 1) + 2]};
                mma_f16(sacc[j], qf[kk], bf, sacc[j]);
            }
        }

        if (t == qt) {
            int row0 = qm0 + wBase + erow, row1 = row0 + 8;
            int colb = t * FBN + q4 * 2;
#pragma unroll
            for (int j = 0; j < 8; j++) {
                int c0 = colb + j * 8, c1 = c0 + 1;
                if (c0 > row0) sacc[j][0] = -1e30f;
                if (c1 > row0) sacc[j][1] = -1e30f;
                if (c0 > row1) sacc[j][2] = -1e30f;
                if (c1 > row1) sacc[j][3] = -1e30f;
            }
        }

        // ---- online softmax in registers
        float mx0 = -1e30f, mx1 = -1e30f;
#pragma unroll
        for (int j = 0; j < 8; j++) {
            mx0 = fmaxf(mx0, fmaxf(sacc[j][0], sacc[j][1]));
            mx1 = fmaxf(mx1, fmaxf(sacc[j][2], sacc[j][3]));
        }
        mx0 = fmaxf(mx0, __shfl_xor_sync(0xFFFFFFFFu, mx0, 1));
        mx0 = fmaxf(mx0, __shfl_xor_sync(0xFFFFFFFFu, mx0, 2));
        mx1 = fmaxf(mx1, __shfl_xor_sync(0xFFFFFFFFu, mx1, 1));
        mx1 = fmaxf(mx1, __shfl_xor_sync(0xFFFFFFFFu, mx1, 2));
        float mn0 = fmaxf(m0, mx0), mn1 = fmaxf(m1, mx1);
        float a0 = __expf(m0 - mn0), a1 = __expf(m1 - mn1);
        float s0 = 0.f, s1 = 0.f;
#pragma unroll
        for (int j = 0; j < 8; j++) {
            float p0 = __expf(sacc[j][0] - mn0); sacc[j][0] = p0; s0 += p0;
            float p1 = __expf(sacc[j][1] - mn0); sacc[j][1] = p1; s0 += p1;
            float p2 = __expf(sacc[j][2] - mn1); sacc[j][2] = p2; s1 += p2;
            float p3 = __expf(sacc[j][3] - mn1); sacc[j][3] = p3; s1 += p3;
        }
        s0 += __shfl_xor_sync(0xFFFFFFFFu, s0, 1);
        s0 += __shfl_xor_sync(0xFFFFFFFFu, s0, 2);
        s1 += __shfl_xor_sync(0xFFFFFFFFu, s1, 1);
        s1 += __shfl_xor_sync(0xFFFFFFFFu, s1, 2);
        l0 = l0 * a0 + s0;
        l1 = l1 * a1 + s1;
        m0 = mn0; m1 = mn1;
#pragma unroll
        for (int jj = 0; jj < 16; jj++) {
            oacc[jj][0] *= a0; oacc[jj][1] *= a0;
            oacc[jj][2] *= a1; oacc[jj][3] *= a1;
        }

        // wait for V_t (K_{t+1} may stay in flight)
        if (t < qt) cp_wait<1>(); else cp_wait<0>();
        __syncthreads();        // all warps done reading K_t

        if (t < qt) {
            flash_load_v(sb + FV_OFF((t + 1) & 1), tid, (t + 1) * FBN, hk, Vth);
            cp_commit();
        }

        // ---- O += (Ph + Pl) @ V  (P split fp16, V single fp16)
#pragma unroll
        for (int tt = 0; tt < 4; tt++) {
            uint32_t ph[4], pl[4];
            {
                __half2 v0 = __floats2half2_rn(sacc[2*tt][0],   sacc[2*tt][1]);
                __half2 v1 = __floats2half2_rn(sacc[2*tt][2],   sacc[2*tt][3]);
                __half2 v2 = __floats2half2_rn(sacc[2*tt+1][0], sacc[2*tt+1][1]);
                __half2 v3 = __floats2half2_rn(sacc[2*tt+1][2], sacc[2*tt+1][3]);
                ph[0] = *(uint32_t*)&v0; ph[1] = *(uint32_t*)&v1;
                ph[2] = *(uint32_t*)&v2; ph[3] = *(uint32_t*)&v3;
                __half2 w0 = __floats2half2_rn(
                    sacc[2*tt][0]   - __half2float(__low2half(v0)),
                    sacc[2*tt][1]   - __half2float(__high2half(v0)));
                __half2 w1 = __floats2half2_rn(
                    sacc[2*tt][2]   - __half2float(__low2half(v1)),
                    sacc[2*tt][3]   - __half2float(__high2half(v1)));
                __half2 w2 = __floats2half2_rn(
                    sacc[2*tt+1][0] - __half2float(__low2half(v2)),
                    sacc[2*tt+1][1] - __half2float(__high2half(v2)));
                __half2 w3 = __floats2half2_rn(
                    sacc[2*tt+1][2] - __half2float(__low2half(v3)),
                    sacc[2*tt+1][3] - __half2float(__high2half(v3)));
                pl[0] = *(uint32_t*)&w0; pl[1] = *(uint32_t*)&w1;
                pl[2] = *(uint32_t*)&w2; pl[3] = *(uint32_t*)&w3;
            }
            int kc = tt >> 1, x = (tt & 1) * 2 + lc;
            uint32_t vbf[8][4];
#pragma unroll
            for (int g = 0; g < 8; g++)
                ldsm_x4(vbf[g], swz(vb + kc * 8192, g * 16 + lr, x));
#pragma unroll
            for (int jj = 0; jj < 16; jj++) {
                uint32_t bf[2] = {vbf[jj >> 1][jj & 1], vbf[jj >> 1][(jj & 1) + 2]};
                mma_f16(oacc[jj], ph, bf, oacc[jj]);
            }
#pragma unroll
            for (int jj = 0; jj < 16; jj++) {
                uint32_t bf[2] = {vbf[jj >> 1][jj & 1], vbf[jj >> 1][(jj & 1) + 2]};
                mma_f16(oacc[jj], pl, bf, oacc[jj]);
            }
        }
    }

    // ---- epilogue: divide by l, split to bf16 hi/lo for the bf16x3 out-proj
    float il0 = 1.0f / l0, il1 = 1.0f / l1;
    int row0 = qm0 + wBase + erow;
#pragma unroll
    for (int jj = 0; jj < 16; jj++) {
        int col = jj * 8 + q4 * 2;
        {
            float o0 = oacc[jj][0] * il0, o1 = oacc[jj][1] * il0;
            __nv_bfloat162 hh = __floats2bfloat162_rn(o0, o1);
            __nv_bfloat162 ll = __floats2bfloat162_rn(o0 - __bfloat162float(hh.x),
                                                      o1 - __bfloat162float(hh.y));
            size_t off = (size_t)row0 * QSTR + h * DHD + col;
            *(__nv_bfloat162*)(Oh + off) = hh;
            *(__nv_bfloat162*)(Ol + off) = ll;
        }
        {
            float o0 = oacc[jj][2] * il1, o1 = oacc[jj][3] * il1;
            __nv_bfloat162 hh = __floats2bfloat162_rn(o0, o1);
            __nv_bfloat162 ll = __floats2bfloat162_rn(o0 - __bfloat162float(hh.x),
                                                      o1 - __bfloat162float(hh.y));
            size_t off = (size_t)(row0 + 8) * QSTR + h * DHD + col;
            *(__nv_bfloat162*)(Oh + off) = hh;
            *(__nv_bfloat162*)(Ol + off) = ll;
        }
    }
}

// ------------------------- launch -----------------------------------------------
extern "C" void kernel_launch(void* const* d_in, const int* in_sizes, int n_in,
                              void* d_out, int out_size)
{
    (void)in_sizes; (void)n_in; (void)out_size;
    const float* hs   = (const float*)d_in[0];
    const float* cosp = (const float*)d_in[1];
    const float* sinp = (const float*)d_in[2];
    const float* wq   = (const float*)d_in[3];
    const float* wk   = (const float*)d_in[4];
    const float* wv   = (const float*)d_in[5];
    const float* wo   = (const float*)d_in[6];
    const float* qnw  = (const float*)d_in[7];
    const float* knw  = (const float*)d_in[8];
    float* out = (float*)d_out;

    float *qp, *kp, *vp;
    cudaGetSymbolAddress((void**)&qp, g_q);
    cudaGetSymbolAddress((void**)&kp, g_k);
    cudaGetSymbolAddress((void**)&vp, g_v);
    __nv_bfloat16 *hsh, *hsl, *ath, *atl;
    __half *qh, *kh, *vth;
    __nv_bfloat16 *wqh, *wql, *wkh, *wkl, *wvh, *wvl, *woh, *wol;
    cudaGetSymbolAddress((void**)&hsh, g_hs_h);
    cudaGetSymbolAddress((void**)&hsl, g_hs_l);
    cudaGetSymbolAddress((void**)&ath, g_at_h);
    cudaGetSymbolAddress((void**)&atl, g_at_l);
    cudaGetSymbolAddress((void**)&qh, g_qh);
    cudaGetSymbolAddress((void**)&kh, g_kh);
    cudaGetSymbolAddress((void**)&vth, g_vth);
    cudaGetSymbolAddress((void**)&wqh, g_wq_h);
    cudaGetSymbolAddress((void**)&wql, g_wq_l);
    cudaGetSymbolAddress((void**)&wkh, g_wk_h);
    cudaGetSymbolAddress((void**)&wkl, g_wk_l);
    cudaGetSymbolAddress((void**)&wvh, g_wv_h);
    cudaGetSymbolAddress((void**)&wvl, g_wv_l);
    cudaGetSymbolAddress((void**)&woh, g_wo_h);
    cudaGetSymbolAddress((void**)&wol, g_wo_l);

    cudaFuncSetAttribute(gemm_qkv, cudaFuncAttributeMaxDynamicSharedMemorySize, G_SMEM);
    cudaFuncSetAttribute(gemm_bf16x3, cudaFuncAttributeMaxDynamicSharedMemorySize, G_SMEM);
    cudaFuncSetAttribute(flash_hmma, cudaFuncAttributeMaxDynamicSharedMemorySize, F_SMEM);

    // 1) input prep: hs split + all weight transposes (one launch)
    prep_inputs<<<18432, 256>>>(hs, wq, wk, wv, wo, hsh, hsl,
                                wqh, wql, wkh, wkl, wvh, wvl, woh, wol);
    // 2) fused QKV projection (bf16x3)
    gemm_qkv<<<dim3(48, S_LEN / 128), 256, G_SMEM>>>(
        hsh, hsl, wqh, wql, wkh, wkl, wvh, wvl, qp, kp, vp);
    // 3) attention prep: rms+rope Q/K -> fp16, V -> transposed fp16 (one launch)
    prep_attn<<<12288, 256>>>(qp, kp, vp, cosp, sinp, qnw, knw, qh, kh, vth);
    // 4) causal flash attention (fp16, 1-pass S + 2-pass PV)
    flash_hmma<<<dim3(S_LEN / FBM, HQ), 128, F_SMEM>>>(qh, kh, vth, ath, atl);
    // 5) output projection (bf16x3)
    gemm_bf16x3<<<dim3(HIDDEN / 64, S_LEN / 128), 256, G_SMEM>>>(
        ath, atl, woh, wol, out, S_LEN, HIDDEN, QSTR);
}

// round 11
// speedup vs baseline: 1.5889x; 1.2285x over previous
#include <cuda_runtime.h>
#include <cuda_bf16.h>
#include <cuda_fp16.h>
#include <math.h>
#include <stdint.h>

#define S_LEN 4096
#define HIDDEN 2048
#define HQ 16
#define HKV 4
#define DHD 128
#define QSTR (HQ*DHD)    // 2048
#define KSTR (HKV*DHD)   // 512
#define RMS_EPS 1e-6f
#define SM_SCALE 0.08838834764831845f  // 128^-0.5

// ------------------------- scratch (static device globals) ----------------------
__device__ float g_q[S_LEN * QSTR];
__device__ float g_k[S_LEN * KSTR];
__device__ float g_v[S_LEN * KSTR];

// fp16 split activations
__device__ __half g_hs_h[S_LEN * HIDDEN];
__device__ __half g_hs_l[S_LEN * HIDDEN];
__device__ __half g_at_h[S_LEN * QSTR];
__device__ __half g_at_l[S_LEN * QSTR];
// flash operands: single fp16 (q, k, v^T)
__device__ __half g_qh[S_LEN * QSTR];
__device__ __half g_kh[S_LEN * KSTR];
__device__ __half g_vth[KSTR * S_LEN];   // [hk*128+d][s]
// transposed weights [N, K] single fp16
__device__ __half g_wq[QSTR * HIDDEN];
__device__ __half g_wk[KSTR * HIDDEN];
__device__ __half g_wv[KSTR * HIDDEN];
__device__ __half g_wo[HIDDEN * QSTR];

// ------------------------- helpers ----------------------------------------------
__device__ __forceinline__ uint32_t smem_u32(const void* p) {
    uint32_t a;
    asm("{ .reg .u64 t; cvta.to.shared.u64 t, %1; cvt.u32.u64 %0, t; }" : "=r"(a) : "l"(p));
    return a;
}
__device__ __forceinline__ void ldsm_x4(uint32_t* r, uint32_t addr) {
    asm volatile("ldmatrix.sync.aligned.m8n8.x4.shared.b16 {%0,%1,%2,%3}, [%4];"
                 : "=r"(r[0]), "=r"(r[1]), "=r"(r[2]), "=r"(r[3]) : "r"(addr));
}
__device__ __forceinline__ void mma_f16(float* d, const uint32_t* a, const uint32_t* b,
                                        const float* c) {
    asm volatile(
        "mma.sync.aligned.m16n8k16.row.col.f32.f16.f16.f32 "
        "{%0,%1,%2,%3}, {%4,%5,%6,%7}, {%8,%9}, {%10,%11,%12,%13};"
        : "=f"(d[0]), "=f"(d[1]), "=f"(d[2]), "=f"(d[3])
        : "r"(a[0]), "r"(a[1]), "r"(a[2]), "r"(a[3]),
          "r"(b[0]), "r"(b[1]),
          "f"(c[0]), "f"(c[1]), "f"(c[2]), "f"(c[3]));
}
__device__ __forceinline__ void cp_async16(uint32_t dst, const void* src) {
    asm volatile("cp.async.cg.shared.global [%0], [%1], 16;" :: "r"(dst), "l"(src) : "memory");
}
__device__ __forceinline__ void cp_commit() {
    asm volatile("cp.async.commit_group;" ::: "memory");
}
template<int N> __device__ __forceinline__ void cp_wait() {
    asm volatile("cp.async.wait_group %0;" :: "n"(N) : "memory");
}
// logical tile rows of 64B (32 b16 elems) with XOR swizzle
__device__ __forceinline__ uint32_t swz(uint32_t tileBase, int r, int c) {
    uint32_t off = r * 64 + c * 16;
    off ^= ((off >> 7) & 7) << 4;
    return tileBase + off;
}

// ------------------------- transpose device core (fp16 single) -------------------
__device__ __forceinline__ void wt_tile_h(
    const float* __restrict__ W, __half* __restrict__ Th,
    int K, int N, int n0, int k0)
{
    __shared__ float t[32][33];
    int tx = threadIdx.x & 31, ty = threadIdx.x >> 5;
#pragma unroll
    for (int j = 0; j < 4; j++)
        t[ty + 8 * j][tx] = W[(size_t)(k0 + ty + 8 * j) * N + n0 + tx];
    __syncthreads();
#pragma unroll
    for (int j = 0; j < 4; j++) {
        size_t o = (size_t)(n0 + ty + 8 * j) * K + k0 + tx;
        Th[o] = __float2half(t[tx][ty + 8 * j]);
    }
}

// merged input prep: hs fp16-split (8192 blocks) + 4 weight transposes (10240)
__global__ __launch_bounds__(256) void prep_inputs(
    const float* __restrict__ hs,
    const float* __restrict__ wq, const float* __restrict__ wk,
    const float* __restrict__ wv, const float* __restrict__ wo,
    __half* __restrict__ hsh, __half* __restrict__ hsl,
    __half* __restrict__ wqt, __half* __restrict__ wkt,
    __half* __restrict__ wvt, __half* __restrict__ wot)
{
    int b = blockIdx.x;
    if (b < 8192) {
        int i = (b * 256 + threadIdx.x) * 4;
        float4 v = *(const float4*)(hs + i);
        __half h0 = __float2half(v.x), h1 = __float2half(v.y);
        __half h2 = __float2half(v.z), h3 = __float2half(v.w);
        __half l0 = __float2half(v.x - __half2float(h0));
        __half l1 = __float2half(v.y - __half2float(h1));
        __half l2 = __float2half(v.z - __half2float(h2));
        __half l3 = __float2half(v.w - __half2float(h3));
        *(__half2*)(hsh + i)     = __halves2half2(h0, h1);
        *(__half2*)(hsh + i + 2) = __halves2half2(h2, h3);
        *(__half2*)(hsl + i)     = __halves2half2(l0, l1);
        *(__half2*)(hsl + i + 2) = __halves2half2(l2, l3);
        return;
    }
    b -= 8192;
    if (b < 4096)
        wt_tile_h(wq, wqt, HIDDEN, QSTR, (b & 63) * 32, (b >> 6) * 32);
    else if (b < 5120) {
        int l = b - 4096;
        wt_tile_h(wk, wkt, HIDDEN, KSTR, (l & 15) * 32, (l >> 4) * 32);
    } else if (b < 6144) {
        int l = b - 5120;
        wt_tile_h(wv, wvt, HIDDEN, KSTR, (l & 15) * 32, (l >> 4) * 32);
    } else {
        int l = b - 6144;
        wt_tile_h(wo, wot, QSTR, HIDDEN, (l & 63) * 32, (l >> 6) * 32);
    }
}

// ------------------------- fp16x2 HMMA GEMM core (K-chunk 64) --------------------
// C = (Ah + Al)[M,K] @ B[N,K]^T.  A split fp16 hi/lo (2 passes), B single fp16.
// CTA 128x64, warp tile 32x32, 8 warps, double-buffered. 80 KB smem, 2 CTAs/SM.
#define GA_SUB 8192                    // 128x32 fp16 subtile
#define GB_SUB 4096                    // 64x32 fp16 subtile
#define GSTAGE (4 * GA_SUB + 2 * GB_SUB)   // 40960
#define G_SMEM (2 * GSTAGE)                // 81920

__device__ __forceinline__ void gemm_stage(
    uint32_t st, int k0, int tid, int K,
    const __half* __restrict__ A0h, const __half* __restrict__ A0l,
    const __half* __restrict__ B0)
{
#pragma unroll
    for (int s2 = 0; s2 < 10; s2++) {
        int i = tid + 256 * s2;
        if (i < 2048) {
            int idx = i >> 9;               // 0..3 : Ah0, Ah1, Al0, Al1
            int r = (i >> 2) & 127, x = i & 3;
            const __half* base = (idx >> 1) ? A0l : A0h;
            cp_async16(swz(st + idx * GA_SUB, r, x),
                       base + (size_t)r * K + k0 + (idx & 1) * 32 + x * 8);
        } else {
            int j = i - 2048;               // 0..511
            int idx = j >> 8;               // 0..1 : B0, B1
            int r = (j >> 2) & 63, x = j & 3;
            cp_async16(swz(st + 4 * GA_SUB + idx * GB_SUB, r, x),
                       B0 + (size_t)r * K + k0 + idx * 32 + x * 8);
        }
    }
    cp_commit();
}

__device__ __forceinline__ void gemm_core(
    const __half* __restrict__ A0h, const __half* __restrict__ A0l,
    const __half* __restrict__ B0,
    float* __restrict__ C0, int ldc, int K, uint32_t sb)
{
    const int tid  = threadIdx.x;
    const int wid  = tid >> 5;
    const int lane = tid & 31;
    const int mBase = (wid >> 1) * 32;
    const int nBase = (wid & 1) * 32;
    const int lr = lane & 15, lc = lane >> 4;

    float acc[2][4][4];
#pragma unroll
    for (int f = 0; f < 2; f++)
#pragma unroll
        for (int j = 0; j < 4; j++)
#pragma unroll
            for (int x = 0; x < 4; x++) acc[f][j][x] = 0.f;

    const int nChunks = K >> 6;
    gemm_stage(sb, 0, tid, K, A0h, A0l, B0);

    for (int kc = 0; kc < nChunks; kc++) {
        const uint32_t st = sb + (kc & 1) * GSTAGE;
        if (kc + 1 < nChunks) {
            gemm_stage(sb + ((kc + 1) & 1) * GSTAGE, (kc + 1) << 6, tid, K,
                       A0h, A0l, B0);
            cp_wait<1>();
        } else {
            cp_wait<0>();
        }
        __syncthreads();

#pragma unroll
        for (int s16 = 0; s16 < 4; s16++) {
            const int sub = s16 >> 1;
            const int ch  = (s16 & 1) * 2 + lc;
            const uint32_t tAh = st + sub * GA_SUB;
            const uint32_t tAl = st + 2 * GA_SUB + sub * GA_SUB;
            const uint32_t tB  = st + 4 * GA_SUB + sub * GB_SUB;

            uint32_t ah[2][4], al[2][4], bb[2][4];
#pragma unroll
            for (int f = 0; f < 2; f++)
                ldsm_x4(ah[f], swz(tAh, mBase + f * 16 + lr, ch));
#pragma unroll
            for (int g = 0; g < 2; g++)
                ldsm_x4(bb[g], swz(tB, nBase + g * 16 + lr, ch));
#pragma unroll
            for (int f = 0; f < 2; f++)
#pragma unroll
                for (int j = 0; j < 4; j++) {
                    uint32_t bfr[2] = {bb[j >> 1][j & 1], bb[j >> 1][2 + (j & 1)]};
                    mma_f16(acc[f][j], ah[f], bfr, acc[f][j]);
                }
#pragma unroll
            for (int f = 0; f < 2; f++)
                ldsm_x4(al[f], swz(tAl, mBase + f * 16 + lr, ch));
#pragma unroll
            for (int f = 0; f < 2; f++)
#pragma unroll
                for (int j = 0; j < 4; j++) {
                    uint32_t bfr[2] = {bb[j >> 1][j & 1], bb[j >> 1][2 + (j & 1)]};
                    mma_f16(acc[f][j], al[f], bfr, acc[f][j]);
                }
        }
        __syncthreads();
    }

    const int erow = lane >> 2;
    const int ecol = (lane & 3) * 2;
#pragma unroll
    for (int f = 0; f < 2; f++) {
        int rl = mBase + f * 16 + erow;
#pragma unroll
        for (int j = 0; j < 4; j++) {
            int cl = nBase + j * 8 + ecol;
            *(float2*)(C0 + (size_t)rl * ldc + cl)       = make_float2(acc[f][j][0], acc[f][j][1]);
            *(float2*)(C0 + (size_t)(rl + 8) * ldc + cl) = make_float2(acc[f][j][2], acc[f][j][3]);
        }
    }
}

// fused QKV projection: grid.x = 48 (32 q, 8 k, 8 v tiles of width 64)
__global__ __launch_bounds__(256, 2) void gemm_qkv(
    const __half* __restrict__ Ah, const __half* __restrict__ Al,
    const __half* __restrict__ wqt, const __half* __restrict__ wkt,
    const __half* __restrict__ wvt,
    float* __restrict__ Q, float* __restrict__ K, float* __restrict__ V)
{
    extern __shared__ char smc[];
    const uint32_t sb = smem_u32(smc);
    const int bx = blockIdx.x;
    const int m0 = blockIdx.y * 128;

    const __half* B;
    float* C;
    int n0, ldc;
    if (bx < 32)      { B = wqt; C = Q; n0 = bx * 64;        ldc = QSTR; }
    else if (bx < 40) { B = wkt; C = K; n0 = (bx - 32) * 64; ldc = KSTR; }
    else              { B = wvt; C = V; n0 = (bx - 40) * 64; ldc = KSTR; }

    gemm_core(Ah + (size_t)m0 * HIDDEN, Al + (size_t)m0 * HIDDEN,
              B + (size_t)n0 * HIDDEN,
              C + (size_t)m0 * ldc + n0, ldc, HIDDEN, sb);
}

// generic single GEMM (output projection)
__global__ __launch_bounds__(256, 2) void gemm_f16x2(
    const __half* __restrict__ Ah, const __half* __restrict__ Al,
    const __half* __restrict__ B,
    float* __restrict__ C, int M, int N, int K)
{
    extern __shared__ char smc[];
    const uint32_t sb = smem_u32(smc);
    const int m0 = blockIdx.y * 128, n0 = blockIdx.x * 64;
    gemm_core(Ah + (size_t)m0 * K, Al + (size_t)m0 * K,
              B + (size_t)n0 * K,
              C + (size_t)m0 * N + n0, N, K, sb);
}

// ------------------------- fused attention prep (one launch) ---------------------
__device__ __forceinline__ void rms_rope_rows_h(
    const float* __restrict__ in, const float* __restrict__ cosp,
    const float* __restrict__ sinp, const float* __restrict__ w,
    int nh, float outScale, int rowBase, __half* __restrict__ H)
{
    const int lane = threadIdx.x & 31;
    const int rowIdx = rowBase + (threadIdx.x >> 5);
    const int s = rowIdx / nh;
    const int d0 = lane * 2;

    const float* x = in + (size_t)rowIdx * DHD;
    float2 a = *(const float2*)(x + d0);
    float2 b = *(const float2*)(x + 64 + d0);

    float ss = a.x * a.x + a.y * a.y + b.x * b.x + b.y * b.y;
#pragma unroll
    for (int o = 16; o > 0; o >>= 1) ss += __shfl_xor_sync(0xFFFFFFFFu, ss, o);
    float inv = rsqrtf(ss * (1.0f / DHD) + RMS_EPS);

    float2 wa = *(const float2*)(w + d0);
    float2 wb = *(const float2*)(w + 64 + d0);
    const float* cs = cosp + (size_t)s * DHD;
    const float* sn = sinp + (size_t)s * DHD;
    float2 ca = *(const float2*)(cs + d0), cb = *(const float2*)(cs + 64 + d0);
    float2 sa = *(const float2*)(sn + d0), sb2 = *(const float2*)(sn + 64 + d0);

    float xa0 = a.x * inv * wa.x, xa1 = a.y * inv * wa.y;
    float xb0 = b.x * inv * wb.x, xb1 = b.y * inv * wb.y;
    float oa0 = (xa0 * ca.x - xb0 * sa.x) * outScale;
    float oa1 = (xa1 * ca.y - xb1 * sa.y) * outScale;
    float ob0 = (xb0 * cb.x + xa0 * sb2.x) * outScale;
    float ob1 = (xb1 * cb.y + xa1 * sb2.y) * outScale;

    size_t off = (size_t)rowIdx * DHD + d0;
    *(__half2*)(H + off)      = __floats2half2_rn(oa0, oa1);
    *(__half2*)(H + off + 64) = __floats2half2_rn(ob0, ob1);
}

__global__ __launch_bounds__(256) void prep_attn(
    const float* __restrict__ qp, const float* __restrict__ kp,
    const float* __restrict__ vp,
    const float* __restrict__ cosp, const float* __restrict__ sinp,
    const float* __restrict__ qnw, const float* __restrict__ knw,
    __half* __restrict__ qh, __half* __restrict__ kh,
    __half* __restrict__ vth)
{
    int b = blockIdx.x;
    if (b < 8192)
        rms_rope_rows_h(qp, cosp, sinp, qnw, HQ, SM_SCALE, b * 8, qh);
    else if (b < 10240)
        rms_rope_rows_h(kp, cosp, sinp, knw, HKV, 1.0f, (b - 8192) * 8, kh);
    else {
        int l = b - 10240;   // vT: 16 x 128 tiles of 32x32
        wt_tile_h(vp, vth, S_LEN, KSTR, (l & 15) * 32, (l >> 4) * 32);
    }
}

// ------------------------- fp16 HMMA causal flash attention ----------------------
#define FBM 64
#define FBN 64
#define FQ_OFF 0
#define FK_OFF(i) (16384 + (i) * 16384)
#define FV_OFF(i) (49152 + (i) * 16384)
#define F_SMEM 81920

__device__ __forceinline__ void flash_load_k(
    uint32_t dst, int tid, int kg0, int hk, const __half* Kh)
{
#pragma unroll
    for (int s = 0; s < 8; s++) {
        int i = tid + 128 * s;
        int c = i >> 8, r = (i >> 2) & 63, x = i & 3;
        cp_async16(swz(dst + c * 4096, r, x),
                   Kh + ((size_t)(kg0 + r) * HKV + hk) * DHD + c * 32 + x * 8);
    }
}
__device__ __forceinline__ void flash_load_v(
    uint32_t dst, int tid, int kg0, int hk, const __half* Vth)
{
#pragma unroll
    for (int s = 0; s < 8; s++) {
        int i = tid + 128 * s;
        int kc = i >> 9, r = (i >> 2) & 127, x = i & 3;
        cp_async16(swz(dst + kc * 8192, r, x),
                   Vth + (size_t)(hk * DHD + r) * S_LEN + kg0 + kc * 32 + x * 8);
    }
}

__global__ __launch_bounds__(128, 2) void flash_hmma(
    const __half* __restrict__ Qh, const __half* __restrict__ Kh,
    const __half* __restrict__ Vth,
    __half* __restrict__ Oh, __half* __restrict__ Ol)
{
    extern __shared__ char smf[];
    const uint32_t sb = smem_u32(smf);
    const int tid = threadIdx.x, wid = tid >> 5, lane = tid & 31;
    const int qt = (int)gridDim.x - 1 - (int)blockIdx.x;   // heavy tiles first
    const int h = blockIdx.y, hk = h >> 2;
    const int qm0 = qt * FBM;
    const int wBase = wid * 16;
    const int lr = lane & 15, lc = lane >> 4;
    const int erow = lane >> 2, q4 = lane & 3;

#pragma unroll
    for (int s = 0; s < 8; s++) {
        int i = tid + 128 * s;
        int c = i >> 8, r = (i >> 2) & 63, x = i & 3;
        cp_async16(swz(sb + FQ_OFF + c * 4096, r, x),
                   Qh + ((size_t)(qm0 + r) * HQ + h) * DHD + c * 32 + x * 8);
    }
    flash_load_k(sb + FK_OFF(0), tid, 0, hk, Kh);
    cp_commit();
    flash_load_v(sb + FV_OFF(0), tid, 0, hk, Vth);
    cp_commit();

    uint32_t qf[8][4];
    float oacc[16][4];
#pragma unroll
    for (int jj = 0; jj < 16; jj++)
#pragma unroll
        for (int x = 0; x < 4; x++) oacc[jj][x] = 0.f;
    float m0 = -1e30f, m1 = -1e30f, l0 = 0.f, l1 = 0.f;

    for (int t = 0; t <= qt; t++) {
        const uint32_t kb = sb + FK_OFF(t & 1);
        const uint32_t vb = sb + FV_OFF(t & 1);

        cp_wait<1>();
        __syncthreads();

        if (t == 0) {
#pragma unroll
            for (int kk = 0; kk < 8; kk++) {
                int c = kk >> 1, x = (kk & 1) * 2 + lc;
                ldsm_x4(qf[kk], swz(sb + FQ_OFF + c * 4096, wBase + lr, x));
            }
        }

        if (t < qt) {
            flash_load_k(sb + FK_OFF((t + 1) & 1), tid, (t + 1) * FBN, hk, Kh);
            cp_commit();
        }

        float sacc[8][4];
#pragma unroll
        for (int j = 0; j < 8; j++)
#pragma unroll
            for (int x = 0; x < 4; x++) sacc[j][x] = 0.f;

#pragma unroll
        for (int kk = 0; kk < 8; kk++) {
            int c = kk >> 1, x = (kk & 1) * 2 + lc;
            uint32_t kbf[4][4];
#pragma unroll
            for (int g = 0; g < 4; g++)
                ldsm_x4(kbf[g], swz(kb + c * 4096, g * 16 + lr, x));
#pragma unroll
            for (int j = 0; j < 8; j++) {
                uint32_t bf[2] = {kbf[j >> 1][j & 1], kbf[j >> 1][(j & 1) + 2]};
                mma_f16(sacc[j], qf[kk], bf, sacc[j]);
            }
        }

        if (t == qt) {
            int row0 = qm0 + wBase + erow, row1 = row0 + 8;
            int colb = t * FBN + q4 * 2;
#pragma unroll
            for (int j = 0; j < 8; j++) {
                int c0 = colb + j * 8, c1 = c0 + 1;
                if (c0 > row0) sacc[j][0] = -1e30f;
                if (c1 > row0) sacc[j][1] = -1e30f;
                if (c0 > row1) sacc[j][2] = -1e30f;
                if (c1 > row1) sacc[j][3] = -1e30f;
            }
        }

        float mx0 = -1e30f, mx1 = -1e30f;
#pragma unroll
        for (int j = 0; j < 8; j++) {
            mx0 = fmaxf(mx0, fmaxf(sacc[j][0], sacc[j][1]));
            mx1 = fmaxf(mx1, fmaxf(sacc[j][2], sacc[j][3]));
        }
        mx0 = fmaxf(mx0, __shfl_xor_sync(0xFFFFFFFFu, mx0, 1));
        mx0 = fmaxf(mx0, __shfl_xor_sync(0xFFFFFFFFu, mx0, 2));
        mx1 = fmaxf(mx1, __shfl_xor_sync(0xFFFFFFFFu, mx1, 1));
        mx1 = fmaxf(mx1, __shfl_xor_sync(0xFFFFFFFFu, mx1, 2));
        float mn0 = fmaxf(m0, mx0), mn1 = fmaxf(m1, mx1);
        float a0 = __expf(m0 - mn0), a1 = __expf(m1 - mn1);
        float s0 = 0.f, s1 = 0.f;
#pragma unroll
        for (int j = 0; j < 8; j++) {
            float p0 = __expf(sacc[j][0] - mn0); sacc[j][0] = p0; s0 += p0;
            float p1 = __expf(sacc[j][1] - mn0); sacc[j][1] = p1; s0 += p1;
            float p2 = __expf(sacc[j][2] - mn1); sacc[j][2] = p2; s1 += p2;
            float p3 = __expf(sacc[j][3] - mn1); sacc[j][3] = p3; s1 += p3;
        }
        s0 += __shfl_xor_sync(0xFFFFFFFFu, s0, 1);
        s0 += __shfl_xor_sync(0xFFFFFFFFu, s0, 2);
        s1 += __shfl_xor_sync(0xFFFFFFFFu, s1, 1);
        s1 += __shfl_xor_sync(0xFFFFFFFFu, s1, 2);
        l0 = l0 * a0 + s0;
        l1 = l1 * a1 + s1;
        m0 = mn0; m1 = mn1;
#pragma unroll
        for (int jj = 0; jj < 16; jj++) {
            oacc[jj][0] *= a0; oacc[jj][1] *= a0;
            oacc[jj][2] *= a1; oacc[jj][3] *= a1;
        }

        if (t < qt) cp_wait<1>(); else cp_wait<0>();
        __syncthreads();

        if (t < qt) {
            flash_load_v(sb + FV_OFF((t + 1) & 1), tid, (t + 1) * FBN, hk, Vth);
            cp_commit();
        }

        // O += (Ph + Pl) @ V
#pragma unroll
        for (int tt = 0; tt < 4; tt++) {
            uint32_t ph[4], pl[4];
            {
                __half2 v0 = __floats2half2_rn(sacc[2*tt][0],   sacc[2*tt][1]);
                __half2 v1 = __floats2half2_rn(sacc[2*tt][2],   sacc[2*tt][3]);
                __half2 v2 = __floats2half2_rn(sacc[2*tt+1][0], sacc[2*tt+1][1]);
                __half2 v3 = __floats2half2_rn(sacc[2*tt+1][2], sacc[2*tt+1][3]);
                ph[0] = *(uint32_t*)&v0; ph[1] = *(uint32_t*)&v1;
                ph[2] = *(uint32_t*)&v2; ph[3] = *(uint32_t*)&v3;
                __half2 w0 = __floats2half2_rn(
                    sacc[2*tt][0]   - __half2float(__low2half(v0)),
                    sacc[2*tt][1]   - __half2float(__high2half(v0)));
                __half2 w1 = __floats2half2_rn(
                    sacc[2*tt][2]   - __half2float(__low2half(v1)),
                    sacc[2*tt][3]   - __half2float(__high2half(v1)));
                __half2 w2 = __floats2half2_rn(
                    sacc[2*tt+1][0] - __half2float(__low2half(v2)),
                    sacc[2*tt+1][1] - __half2float(__high2half(v2)));
                __half2 w3 = __floats2half2_rn(
                    sacc[2*tt+1][2] - __half2float(__low2half(v3)),
                    sacc[2*tt+1][3] - __half2float(__high2half(v3)));
                pl[0] = *(uint32_t*)&w0; pl[1] = *(uint32_t*)&w1;
                pl[2] = *(uint32_t*)&w2; pl[3] = *(uint32_t*)&w3;
            }
            int kc = tt >> 1, x = (tt & 1) * 2 + lc;
            uint32_t vbf[8][4];
#pragma unroll
            for (int g = 0; g < 8; g++)
                ldsm_x4(vbf[g], swz(vb + kc * 8192, g * 16 + lr, x));
#pragma unroll
            for (int jj = 0; jj < 16; jj++) {
                uint32_t bf[2] = {vbf[jj >> 1][jj & 1], vbf[jj >> 1][(jj & 1) + 2]};
                mma_f16(oacc[jj], ph, bf, oacc[jj]);
            }
#pragma unroll
            for (int jj = 0; jj < 16; jj++) {
                uint32_t bf[2] = {vbf[jj >> 1][jj & 1], vbf[jj >> 1][(jj & 1) + 2]};
                mma_f16(oacc[jj], pl, bf, oacc[jj]);
            }
        }
    }

    // epilogue: divide by l, split to fp16 hi/lo for fp16x2 out-proj
    float il0 = 1.0f / l0, il1 = 1.0f / l1;
    int row0 = qm0 + wBase + erow;
#pragma unroll
    for (int jj = 0; jj < 16; jj++) {
        int col = jj * 8 + q4 * 2;
        {
            float o0 = oacc[jj][0] * il0, o1 = oacc[jj][1] * il0;
            __half2 hh = __floats2half2_rn(o0, o1);
            __half2 ll = __floats2half2_rn(o0 - __half2float(__low2half(hh)),
                                           o1 - __half2float(__high2half(hh)));
            size_t off = (size_t)row0 * QSTR + h * DHD + col;
            *(__half2*)(Oh + off) = hh;
            *(__half2*)(Ol + off) = ll;
        }
        {
            float o0 = oacc[jj][2] * il1, o1 = oacc[jj][3] * il1;
            __half2 hh = __floats2half2_rn(o0, o1);
            __half2 ll = __floats2half2_rn(o0 - __half2float(__low2half(hh)),
                                           o1 - __half2float(__high2half(hh)));
            size_t off = (size_t)(row0 + 8) * QSTR + h * DHD + col;
            *(__half2*)(Oh + off) = hh;
            *(__half2*)(Ol + off) = ll;
        }
    }
}

// ------------------------- launch -----------------------------------------------
extern "C" void kernel_launch(void* const* d_in, const int* in_sizes, int n_in,
                              void* d_out, int out_size)
{
    (void)in_sizes; (void)n_in; (void)out_size;
    const float* hs   = (const float*)d_in[0];
    const float* cosp = (const float*)d_in[1];
    const float* sinp = (const float*)d_in[2];
    const float* wq   = (const float*)d_in[3];
    const float* wk   = (const float*)d_in[4];
    const float* wv   = (const float*)d_in[5];
    const float* wo   = (const float*)d_in[6];
    const float* qnw  = (const float*)d_in[7];
    const float* knw  = (const float*)d_in[8];
    float* out = (float*)d_out;

    float *qp, *kp, *vp;
    cudaGetSymbolAddress((void**)&qp, g_q);
    cudaGetSymbolAddress((void**)&kp, g_k);
    cudaGetSymbolAddress((void**)&vp, g_v);
    __half *hsh, *hsl, *ath, *atl, *qh, *kh, *vth;
    __half *wqt, *wkt, *wvt, *wot;
    cudaGetSymbolAddress((void**)&hsh, g_hs_h);
    cudaGetSymbolAddress((void**)&hsl, g_hs_l);
    cudaGetSymbolAddress((void**)&ath, g_at_h);
    cudaGetSymbolAddress((void**)&atl, g_at_l);
    cudaGetSymbolAddress((void**)&qh, g_qh);
    cudaGetSymbolAddress((void**)&kh, g_kh);
    cudaGetSymbolAddress((void**)&vth, g_vth);
    cudaGetSymbolAddress((void**)&wqt, g_wq);
    cudaGetSymbolAddress((void**)&wkt, g_wk);
    cudaGetSymbolAddress((void**)&wvt, g_wv);
    cudaGetSymbolAddress((void**)&wot, g_wo);

    cudaFuncSetAttribute(gemm_qkv, cudaFuncAttributeMaxDynamicSharedMemorySize, G_SMEM);
    cudaFuncSetAttribute(gemm_f16x2, cudaFuncAttributeMaxDynamicSharedMemorySize, G_SMEM);
    cudaFuncSetAttribute(flash_hmma, cudaFuncAttributeMaxDynamicSharedMemorySize, F_SMEM);

    // 1) input prep: hs fp16 split + weight transposes (one launch)
    prep_inputs<<<18432, 256>>>(hs, wq, wk, wv, wo, hsh, hsl,
                                wqt, wkt, wvt, wot);
    // 2) fused QKV projection (fp16x2)
    gemm_qkv<<<dim3(48, S_LEN / 128), 256, G_SMEM>>>(
        hsh, hsl, wqt, wkt, wvt, qp, kp, vp);
    // 3) attention prep: rms+rope Q/K -> fp16, V -> transposed fp16
    prep_attn<<<12288, 256>>>(qp, kp, vp, cosp, sinp, qnw, knw, qh, kh, vth);
    // 4) causal flash attention (fp16, 1-pass S + 2-pass PV)
    flash_hmma<<<dim3(S_LEN / FBM, HQ), 128, F_SMEM>>>(qh, kh, vth, ath, atl);
    // 5) output projection (fp16x2)
    gemm_f16x2<<<dim3(HIDDEN / 64, S_LEN / 128), 256, G_SMEM>>>(
        ath, atl, wot, out, S_LEN, HIDDEN, QSTR);
}

// round 12
// speedup vs baseline: 1.7672x; 1.1122x over previous
#include <cuda_runtime.h>
#include <cuda_bf16.h>
#include <cuda_fp16.h>
#include <math.h>
#include <stdint.h>

#define S_LEN 4096
#define HIDDEN 2048
#define HQ 16
#define HKV 4
#define DHD 128
#define QSTR (HQ*DHD)    // 2048
#define KSTR (HKV*DHD)   // 512
#define RMS_EPS 1e-6f
#define SM_SCALE 0.08838834764831845f  // 128^-0.5

// ------------------------- scratch (static device globals) ----------------------
__device__ float g_q[S_LEN * QSTR];
__device__ float g_k[S_LEN * KSTR];
__device__ float g_v[S_LEN * KSTR];

// fp16 split activations
__device__ __half g_hs_h[S_LEN * HIDDEN];
__device__ __half g_hs_l[S_LEN * HIDDEN];
__device__ __half g_at_h[S_LEN * QSTR];
__device__ __half g_at_l[S_LEN * QSTR];
// flash operands: single fp16 (q, k, v^T)
__device__ __half g_qh[S_LEN * QSTR];
__device__ __half g_kh[S_LEN * KSTR];
__device__ __half g_vth[KSTR * S_LEN];   // [hk*128+d][s]
// transposed weights [N, K] single fp16
__device__ __half g_wq[QSTR * HIDDEN];
__device__ __half g_wk[KSTR * HIDDEN];
__device__ __half g_wv[KSTR * HIDDEN];
__device__ __half g_wo[HIDDEN * QSTR];

// ------------------------- helpers ----------------------------------------------
__device__ __forceinline__ uint32_t smem_u32(const void* p) {
    uint32_t a;
    asm("{ .reg .u64 t; cvta.to.shared.u64 t, %1; cvt.u32.u64 %0, t; }" : "=r"(a) : "l"(p));
    return a;
}
__device__ __forceinline__ void ldsm_x4(uint32_t* r, uint32_t addr) {
    asm volatile("ldmatrix.sync.aligned.m8n8.x4.shared.b16 {%0,%1,%2,%3}, [%4];"
                 : "=r"(r[0]), "=r"(r[1]), "=r"(r[2]), "=r"(r[3]) : "r"(addr));
}
__device__ __forceinline__ void mma_f16(float* d, const uint32_t* a, const uint32_t* b,
                                        const float* c) {
    asm volatile(
        "mma.sync.aligned.m16n8k16.row.col.f32.f16.f16.f32 "
        "{%0,%1,%2,%3}, {%4,%5,%6,%7}, {%8,%9}, {%10,%11,%12,%13};"
        : "=f"(d[0]), "=f"(d[1]), "=f"(d[2]), "=f"(d[3])
        : "r"(a[0]), "r"(a[1]), "r"(a[2]), "r"(a[3]),
          "r"(b[0]), "r"(b[1]),
          "f"(c[0]), "f"(c[1]), "f"(c[2]), "f"(c[3]));
}
__device__ __forceinline__ void cp_async16(uint32_t dst, const void* src) {
    asm volatile("cp.async.cg.shared.global [%0], [%1], 16;" :: "r"(dst), "l"(src) : "memory");
}
__device__ __forceinline__ void cp_commit() {
    asm volatile("cp.async.commit_group;" ::: "memory");
}
template<int N> __device__ __forceinline__ void cp_wait() {
    asm volatile("cp.async.wait_group %0;" :: "n"(N) : "memory");
}
// logical tile rows of 64B (32 b16 elems) with XOR swizzle
__device__ __forceinline__ uint32_t swz(uint32_t tileBase, int r, int c) {
    uint32_t off = r * 64 + c * 16;
    off ^= ((off >> 7) & 7) << 4;
    return tileBase + off;
}

// ------------------------- transpose device core (fp16 single) -------------------
__device__ __forceinline__ void wt_tile_h(
    const float* __restrict__ W, __half* __restrict__ Th,
    int K, int N, int n0, int k0)
{
    __shared__ float t[32][33];
    int tx = threadIdx.x & 31, ty = threadIdx.x >> 5;
#pragma unroll
    for (int j = 0; j < 4; j++)
        t[ty + 8 * j][tx] = W[(size_t)(k0 + ty + 8 * j) * N + n0 + tx];
    __syncthreads();
#pragma unroll
    for (int j = 0; j < 4; j++) {
        size_t o = (size_t)(n0 + ty + 8 * j) * K + k0 + tx;
        Th[o] = __float2half(t[tx][ty + 8 * j]);
    }
}

// merged input prep: hs fp16-split (8192 blocks) + 4 weight transposes (10240)
__global__ __launch_bounds__(256) void prep_inputs(
    const float* __restrict__ hs,
    const float* __restrict__ wq, const float* __restrict__ wk,
    const float* __restrict__ wv, const float* __restrict__ wo,
    __half* __restrict__ hsh, __half* __restrict__ hsl,
    __half* __restrict__ wqt, __half* __restrict__ wkt,
    __half* __restrict__ wvt, __half* __restrict__ wot)
{
    int b = blockIdx.x;
    if (b < 8192) {
        int i = (b * 256 + threadIdx.x) * 4;
        float4 v = *(const float4*)(hs + i);
        __half h0 = __float2half(v.x), h1 = __float2half(v.y);
        __half h2 = __float2half(v.z), h3 = __float2half(v.w);
        __half l0 = __float2half(v.x - __half2float(h0));
        __half l1 = __float2half(v.y - __half2float(h1));
        __half l2 = __float2half(v.z - __half2float(h2));
        __half l3 = __float2half(v.w - __half2float(h3));
        *(__half2*)(hsh + i)     = __halves2half2(h0, h1);
        *(__half2*)(hsh + i + 2) = __halves2half2(h2, h3);
        *(__half2*)(hsl + i)     = __halves2half2(l0, l1);
        *(__half2*)(hsl + i + 2) = __halves2half2(l2, l3);
        return;
    }
    b -= 8192;
    if (b < 4096)
        wt_tile_h(wq, wqt, HIDDEN, QSTR, (b & 63) * 32, (b >> 6) * 32);
    else if (b < 5120) {
        int l = b - 4096;
        wt_tile_h(wk, wkt, HIDDEN, KSTR, (l & 15) * 32, (l >> 4) * 32);
    } else if (b < 6144) {
        int l = b - 5120;
        wt_tile_h(wv, wvt, HIDDEN, KSTR, (l & 15) * 32, (l >> 4) * 32);
    } else {
        int l = b - 6144;
        wt_tile_h(wo, wot, QSTR, HIDDEN, (l & 63) * 32, (l >> 6) * 32);
    }
}

// ------------------------- fp16x2 HMMA GEMM core (K-chunk 64) --------------------
#define GA_SUB 8192
#define GB_SUB 4096
#define GSTAGE (4 * GA_SUB + 2 * GB_SUB)   // 40960
#define G_SMEM (2 * GSTAGE)                // 81920

__device__ __forceinline__ void gemm_stage(
    uint32_t st, int k0, int tid, int K,
    const __half* __restrict__ A0h, const __half* __restrict__ A0l,
    const __half* __restrict__ B0)
{
#pragma unroll
    for (int s2 = 0; s2 < 10; s2++) {
        int i = tid + 256 * s2;
        if (i < 2048) {
            int idx = i >> 9;
            int r = (i >> 2) & 127, x = i & 3;
            const __half* base = (idx >> 1) ? A0l : A0h;
            cp_async16(swz(st + idx * GA_SUB, r, x),
                       base + (size_t)r * K + k0 + (idx & 1) * 32 + x * 8);
        } else {
            int j = i - 2048;
            int idx = j >> 8;
            int r = (j >> 2) & 63, x = j & 3;
            cp_async16(swz(st + 4 * GA_SUB + idx * GB_SUB, r, x),
                       B0 + (size_t)r * K + k0 + idx * 32 + x * 8);
        }
    }
    cp_commit();
}

__device__ __forceinline__ void gemm_core(
    const __half* __restrict__ A0h, const __half* __restrict__ A0l,
    const __half* __restrict__ B0,
    float* __restrict__ C0, int ldc, int K, uint32_t sb)
{
    const int tid  = threadIdx.x;
    const int wid  = tid >> 5;
    const int lane = tid & 31;
    const int mBase = (wid >> 1) * 32;
    const int nBase = (wid & 1) * 32;
    const int lr = lane & 15, lc = lane >> 4;

    float acc[2][4][4];
#pragma unroll
    for (int f = 0; f < 2; f++)
#pragma unroll
        for (int j = 0; j < 4; j++)
#pragma unroll
            for (int x = 0; x < 4; x++) acc[f][j][x] = 0.f;

    const int nChunks = K >> 6;
    gemm_stage(sb, 0, tid, K, A0h, A0l, B0);

    for (int kc = 0; kc < nChunks; kc++) {
        const uint32_t st = sb + (kc & 1) * GSTAGE;
        if (kc + 1 < nChunks) {
            gemm_stage(sb + ((kc + 1) & 1) * GSTAGE, (kc + 1) << 6, tid, K,
                       A0h, A0l, B0);
            cp_wait<1>();
        } else {
            cp_wait<0>();
        }
        __syncthreads();

#pragma unroll
        for (int s16 = 0; s16 < 4; s16++) {
            const int sub = s16 >> 1;
            const int ch  = (s16 & 1) * 2 + lc;
            const uint32_t tAh = st + sub * GA_SUB;
            const uint32_t tAl = st + 2 * GA_SUB + sub * GA_SUB;
            const uint32_t tB  = st + 4 * GA_SUB + sub * GB_SUB;

            uint32_t ah[2][4], al[2][4], bb[2][4];
#pragma unroll
            for (int f = 0; f < 2; f++)
                ldsm_x4(ah[f], swz(tAh, mBase + f * 16 + lr, ch));
#pragma unroll
            for (int g = 0; g < 2; g++)
                ldsm_x4(bb[g], swz(tB, nBase + g * 16 + lr, ch));
#pragma unroll
            for (int f = 0; f < 2; f++)
#pragma unroll
                for (int j = 0; j < 4; j++) {
                    uint32_t bfr[2] = {bb[j >> 1][j & 1], bb[j >> 1][2 + (j & 1)]};
                    mma_f16(acc[f][j], ah[f], bfr, acc[f][j]);
                }
#pragma unroll
            for (int f = 0; f < 2; f++)
                ldsm_x4(al[f], swz(tAl, mBase + f * 16 + lr, ch));
#pragma unroll
            for (int f = 0; f < 2; f++)
#pragma unroll
                for (int j = 0; j < 4; j++) {
                    uint32_t bfr[2] = {bb[j >> 1][j & 1], bb[j >> 1][2 + (j & 1)]};
                    mma_f16(acc[f][j], al[f], bfr, acc[f][j]);
                }
        }
        __syncthreads();
    }

    const int erow = lane >> 2;
    const int ecol = (lane & 3) * 2;
#pragma unroll
    for (int f = 0; f < 2; f++) {
        int rl = mBase + f * 16 + erow;
#pragma unroll
        for (int j = 0; j < 4; j++) {
            int cl = nBase + j * 8 + ecol;
            *(float2*)(C0 + (size_t)rl * ldc + cl)       = make_float2(acc[f][j][0], acc[f][j][1]);
            *(float2*)(C0 + (size_t)(rl + 8) * ldc + cl) = make_float2(acc[f][j][2], acc[f][j][3]);
        }
    }
}

__global__ __launch_bounds__(256, 2) void gemm_qkv(
    const __half* __restrict__ Ah, const __half* __restrict__ Al,
    const __half* __restrict__ wqt, const __half* __restrict__ wkt,
    const __half* __restrict__ wvt,
    float* __restrict__ Q, float* __restrict__ K, float* __restrict__ V)
{
    extern __shared__ char smc[];
    const uint32_t sb = smem_u32(smc);
    const int bx = blockIdx.x;
    const int m0 = blockIdx.y * 128;

    const __half* B;
    float* C;
    int n0, ldc;
    if (bx < 32)      { B = wqt; C = Q; n0 = bx * 64;        ldc = QSTR; }
    else if (bx < 40) { B = wkt; C = K; n0 = (bx - 32) * 64; ldc = KSTR; }
    else              { B = wvt; C = V; n0 = (bx - 40) * 64; ldc = KSTR; }

    gemm_core(Ah + (size_t)m0 * HIDDEN, Al + (size_t)m0 * HIDDEN,
              B + (size_t)n0 * HIDDEN,
              C + (size_t)m0 * ldc + n0, ldc, HIDDEN, sb);
}

__global__ __launch_bounds__(256, 2) void gemm_f16x2(
    const __half* __restrict__ Ah, const __half* __restrict__ Al,
    const __half* __restrict__ B,
    float* __restrict__ C, int M, int N, int K)
{
    extern __shared__ char smc[];
    const uint32_t sb = smem_u32(smc);
    const int m0 = blockIdx.y * 128, n0 = blockIdx.x * 64;
    gemm_core(Ah + (size_t)m0 * K, Al + (size_t)m0 * K,
              B + (size_t)n0 * K,
              C + (size_t)m0 * N + n0, N, K, sb);
}

// ------------------------- fused attention prep (one launch) ---------------------
__device__ __forceinline__ void rms_rope_rows_h(
    const float* __restrict__ in, const float* __restrict__ cosp,
    const float* __restrict__ sinp, const float* __restrict__ w,
    int nh, float outScale, int rowBase, __half* __restrict__ H)
{
    const int lane = threadIdx.x & 31;
    const int rowIdx = rowBase + (threadIdx.x >> 5);
    const int s = rowIdx / nh;
    const int d0 = lane * 2;

    const float* x = in + (size_t)rowIdx * DHD;
    float2 a = *(const float2*)(x + d0);
    float2 b = *(const float2*)(x + 64 + d0);

    float ss = a.x * a.x + a.y * a.y + b.x * b.x + b.y * b.y;
#pragma unroll
    for (int o = 16; o > 0; o >>= 1) ss += __shfl_xor_sync(0xFFFFFFFFu, ss, o);
    float inv = rsqrtf(ss * (1.0f / DHD) + RMS_EPS);

    float2 wa = *(const float2*)(w + d0);
    float2 wb = *(const float2*)(w + 64 + d0);
    const float* cs = cosp + (size_t)s * DHD;
    const float* sn = sinp + (size_t)s * DHD;
    float2 ca = *(const float2*)(cs + d0), cb = *(const float2*)(cs + 64 + d0);
    float2 sa = *(const float2*)(sn + d0), sb2 = *(const float2*)(sn + 64 + d0);

    float xa0 = a.x * inv * wa.x, xa1 = a.y * inv * wa.y;
    float xb0 = b.x * inv * wb.x, xb1 = b.y * inv * wb.y;
    float oa0 = (xa0 * ca.x - xb0 * sa.x) * outScale;
    float oa1 = (xa1 * ca.y - xb1 * sa.y) * outScale;
    float ob0 = (xb0 * cb.x + xa0 * sb2.x) * outScale;
    float ob1 = (xb1 * cb.y + xa1 * sb2.y) * outScale;

    size_t off = (size_t)rowIdx * DHD + d0;
    *(__half2*)(H + off)      = __floats2half2_rn(oa0, oa1);
    *(__half2*)(H + off + 64) = __floats2half2_rn(ob0, ob1);
}

__global__ __launch_bounds__(256) void prep_attn(
    const float* __restrict__ qp, const float* __restrict__ kp,
    const float* __restrict__ vp,
    const float* __restrict__ cosp, const float* __restrict__ sinp,
    const float* __restrict__ qnw, const float* __restrict__ knw,
    __half* __restrict__ qh, __half* __restrict__ kh,
    __half* __restrict__ vth)
{
    int b = blockIdx.x;
    if (b < 8192)
        rms_rope_rows_h(qp, cosp, sinp, qnw, HQ, SM_SCALE, b * 8, qh);
    else if (b < 10240)
        rms_rope_rows_h(kp, cosp, sinp, knw, HKV, 1.0f, (b - 8192) * 8, kh);
    else {
        int l = b - 10240;
        wt_tile_h(vp, vth, S_LEN, KSTR, (l & 15) * 32, (l >> 4) * 32);
    }
}

// ------------------------- fp16 HMMA causal flash attention ----------------------
// 1-pass S (fp16 q,k), 1-pass PV (fp16 p,v). Double-buffered K/V slots.
#define FBM 64
#define FBN 64
#define FQ_OFF 0
#define FK_OFF(i) (16384 + (i) * 16384)
#define FV_OFF(i) (49152 + (i) * 16384)
#define F_SMEM 81920

__device__ __forceinline__ void flash_load_k(
    uint32_t dst, int tid, int kg0, int hk, const __half* Kh)
{
#pragma unroll
    for (int s = 0; s < 8; s++) {
        int i = tid + 128 * s;
        int c = i >> 8, r = (i >> 2) & 63, x = i & 3;
        cp_async16(swz(dst + c * 4096, r, x),
                   Kh + ((size_t)(kg0 + r) * HKV + hk) * DHD + c * 32 + x * 8);
    }
}
__device__ __forceinline__ void flash_load_v(
    uint32_t dst, int tid, int kg0, int hk, const __half* Vth)
{
#pragma unroll
    for (int s = 0; s < 8; s++) {
        int i = tid + 128 * s;
        int kc = i >> 9, r = (i >> 2) & 127, x = i & 3;
        cp_async16(swz(dst + kc * 8192, r, x),
                   Vth + (size_t)(hk * DHD + r) * S_LEN + kg0 + kc * 32 + x * 8);
    }
}

__global__ __launch_bounds__(128, 2) void flash_hmma(
    const __half* __restrict__ Qh, const __half* __restrict__ Kh,
    const __half* __restrict__ Vth,
    __half* __restrict__ Oh, __half* __restrict__ Ol)
{
    extern __shared__ char smf[];
    const uint32_t sb = smem_u32(smf);
    const int tid = threadIdx.x, wid = tid >> 5, lane = tid & 31;
    const int qt = (int)gridDim.x - 1 - (int)blockIdx.x;   // heavy tiles first
    const int h = blockIdx.y, hk = h >> 2;
    const int qm0 = qt * FBM;
    const int wBase = wid * 16;
    const int lr = lane & 15, lc = lane >> 4;
    const int erow = lane >> 2, q4 = lane & 3;

#pragma unroll
    for (int s = 0; s < 8; s++) {
        int i = tid + 128 * s;
        int c = i >> 8, r = (i >> 2) & 63, x = i & 3;
        cp_async16(swz(sb + FQ_OFF + c * 4096, r, x),
                   Qh + ((size_t)(qm0 + r) * HQ + h) * DHD + c * 32 + x * 8);
    }
    flash_load_k(sb + FK_OFF(0), tid, 0, hk, Kh);
    cp_commit();
    flash_load_v(sb + FV_OFF(0), tid, 0, hk, Vth);
    cp_commit();

    uint32_t qf[8][4];
    float oacc[16][4];
#pragma unroll
    for (int jj = 0; jj < 16; jj++)
#pragma unroll
        for (int x = 0; x < 4; x++) oacc[jj][x] = 0.f;
    float m0 = -1e30f, m1 = -1e30f, l0 = 0.f, l1 = 0.f;

    for (int t = 0; t <= qt; t++) {
        const uint32_t kb = sb + FK_OFF(t & 1);
        const uint32_t vb = sb + FV_OFF(t & 1);

        cp_wait<1>();
        __syncthreads();

        if (t == 0) {
#pragma unroll
            for (int kk = 0; kk < 8; kk++) {
                int c = kk >> 1, x = (kk & 1) * 2 + lc;
                ldsm_x4(qf[kk], swz(sb + FQ_OFF + c * 4096, wBase + lr, x));
            }
        }

        if (t < qt) {
            flash_load_k(sb + FK_OFF((t + 1) & 1), tid, (t + 1) * FBN, hk, Kh);
            cp_commit();
        }

        float sacc[8][4];
#pragma unroll
        for (int j = 0; j < 8; j++)
#pragma unroll
            for (int x = 0; x < 4; x++) sacc[j][x] = 0.f;

#pragma unroll
        for (int kk = 0; kk < 8; kk++) {
            int c = kk >> 1, x = (kk & 1) * 2 + lc;
            uint32_t kbf[4][4];
#pragma unroll
            for (int g = 0; g < 4; g++)
                ldsm_x4(kbf[g], swz(kb + c * 4096, g * 16 + lr, x));
#pragma unroll
            for (int j = 0; j < 8; j++) {
                uint32_t bf[2] = {kbf[j >> 1][j & 1], kbf[j >> 1][(j & 1) + 2]};
                mma_f16(sacc[j], qf[kk], bf, sacc[j]);
            }
        }

        if (t == qt) {
            int row0 = qm0 + wBase + erow, row1 = row0 + 8;
            int colb = t * FBN + q4 * 2;
#pragma unroll
            for (int j = 0; j < 8; j++) {
                int c0 = colb + j * 8, c1 = c0 + 1;
                if (c0 > row0) sacc[j][0] = -1e30f;
                if (c1 > row0) sacc[j][1] = -1e30f;
                if (c0 > row1) sacc[j][2] = -1e30f;
                if (c1 > row1) sacc[j][3] = -1e30f;
            }
        }

        float mx0 = -1e30f, mx1 = -1e30f;
#pragma unroll
        for (int j = 0; j < 8; j++) {
            mx0 = fmaxf(mx0, fmaxf(sacc[j][0], sacc[j][1]));
            mx1 = fmaxf(mx1, fmaxf(sacc[j][2], sacc[j][3]));
        }
        mx0 = fmaxf(mx0, __shfl_xor_sync(0xFFFFFFFFu, mx0, 1));
        mx0 = fmaxf(mx0, __shfl_xor_sync(0xFFFFFFFFu, mx0, 2));
        mx1 = fmaxf(mx1, __shfl_xor_sync(0xFFFFFFFFu, mx1, 1));
        mx1 = fmaxf(mx1, __shfl_xor_sync(0xFFFFFFFFu, mx1, 2));
        float mn0 = fmaxf(m0, mx0), mn1 = fmaxf(m1, mx1);
        float a0 = __expf(m0 - mn0), a1 = __expf(m1 - mn1);
        float s0 = 0.f, s1 = 0.f;
#pragma unroll
        for (int j = 0; j < 8; j++) {
            float p0 = __expf(sacc[j][0] - mn0); sacc[j][0] = p0; s0 += p0;
            float p1 = __expf(sacc[j][1] - mn0); sacc[j][1] = p1; s0 += p1;
            float p2 = __expf(sacc[j][2] - mn1); sacc[j][2] = p2; s1 += p2;
            float p3 = __expf(sacc[j][3] - mn1); sacc[j][3] = p3; s1 += p3;
        }
        s0 += __shfl_xor_sync(0xFFFFFFFFu, s0, 1);
        s0 += __shfl_xor_sync(0xFFFFFFFFu, s0, 2);
        s1 += __shfl_xor_sync(0xFFFFFFFFu, s1, 1);
        s1 += __shfl_xor_sync(0xFFFFFFFFu, s1, 2);
        l0 = l0 * a0 + s0;
        l1 = l1 * a1 + s1;
        m0 = mn0; m1 = mn1;
#pragma unroll
        for (int jj = 0; jj < 16; jj++) {
            oacc[jj][0] *= a0; oacc[jj][1] *= a0;
            oacc[jj][2] *= a1; oacc[jj][3] *= a1;
        }

        if (t < qt) cp_wait<1>(); else cp_wait<0>();
        __syncthreads();

        if (t < qt) {
            flash_load_v(sb + FV_OFF((t + 1) & 1), tid, (t + 1) * FBN, hk, Vth);
            cp_commit();
        }

        // O += P @ V  (single fp16 P)
#pragma unroll
        for (int tt = 0; tt < 4; tt++) {
            uint32_t ph[4];
            {
                __half2 v0 = __floats2half2_rn(sacc[2*tt][0],   sacc[2*tt][1]);
                __half2 v1 = __floats2half2_rn(sacc[2*tt][2],   sacc[2*tt][3]);
                __half2 v2 = __floats2half2_rn(sacc[2*tt+1][0], sacc[2*tt+1][1]);
                __half2 v3 = __floats2half2_rn(sacc[2*tt+1][2], sacc[2*tt+1][3]);
                ph[0] = *(uint32_t*)&v0; ph[1] = *(uint32_t*)&v1;
                ph[2] = *(uint32_t*)&v2; ph[3] = *(uint32_t*)&v3;
            }
            int kc = tt >> 1, x = (tt & 1) * 2 + lc;
            uint32_t vbf[8][4];
#pragma unroll
            for (int g = 0; g < 8; g++)
                ldsm_x4(vbf[g], swz(vb + kc * 8192, g * 16 + lr, x));
#pragma unroll
            for (int jj = 0; jj < 16; jj++) {
                uint32_t bf[2] = {vbf[jj >> 1][jj & 1], vbf[jj >> 1][(jj & 1) + 2]};
                mma_f16(oacc[jj], ph, bf, oacc[jj]);
            }
        }
    }

    // epilogue: divide by l, split to fp16 hi/lo for fp16x2 out-proj
    float il0 = 1.0f / l0, il1 = 1.0f / l1;
    int row0 = qm0 + wBase + erow;
#pragma unroll
    for (int jj = 0; jj < 16; jj++) {
        int col = jj * 8 + q4 * 2;
        {
            float o0 = oacc[jj][0] * il0, o1 = oacc[jj][1] * il0;
            __half2 hh = __floats2half2_rn(o0, o1);
            __half2 ll = __floats2half2_rn(o0 - __half2float(__low2half(hh)),
                                           o1 - __half2float(__high2half(hh)));
            size_t off = (size_t)row0 * QSTR + h * DHD + col;
            *(__half2*)(Oh + off) = hh;
            *(__half2*)(Ol + off) = ll;
        }
        {
            float o0 = oacc[jj][2] * il1, o1 = oacc[jj][3] * il1;
            __half2 hh = __floats2half2_rn(o0, o1);
            __half2 ll = __floats2half2_rn(o0 - __half2float(__low2half(hh)),
                                           o1 - __half2float(__high2half(hh)));
            size_t off = (size_t)(row0 + 8) * QSTR + h * DHD + col;
            *(__half2*)(Oh + off) = hh;
            *(__half2*)(Ol + off) = ll;
        }
    }
}

// ------------------------- launch -----------------------------------------------
extern "C" void kernel_launch(void* const* d_in, const int* in_sizes, int n_in,
                              void* d_out, int out_size)
{
    (void)in_sizes; (void)n_in; (void)out_size;
    const float* hs   = (const float*)d_in[0];
    const float* cosp = (const float*)d_in[1];
    const float* sinp = (const float*)d_in[2];
    const float* wq   = (const float*)d_in[3];
    const float* wk   = (const float*)d_in[4];
    const float* wv   = (const float*)d_in[5];
    const float* wo   = (const float*)d_in[6];
    const float* qnw  = (const float*)d_in[7];
    const float* knw  = (const float*)d_in[8];
    float* out = (float*)d_out;

    float *qp, *kp, *vp;
    cudaGetSymbolAddress((void**)&qp, g_q);
    cudaGetSymbolAddress((void**)&kp, g_k);
    cudaGetSymbolAddress((void**)&vp, g_v);
    __half *hsh, *hsl, *ath, *atl, *qh, *kh, *vth;
    __half *wqt, *wkt, *wvt, *wot;
    cudaGetSymbolAddress((void**)&hsh, g_hs_h);
    cudaGetSymbolAddress((void**)&hsl, g_hs_l);
    cudaGetSymbolAddress((void**)&ath, g_at_h);
    cudaGetSymbolAddress((void**)&atl, g_at_l);
    cudaGetSymbolAddress((void**)&qh, g_qh);
    cudaGetSymbolAddress((void**)&kh, g_kh);
    cudaGetSymbolAddress((void**)&vth, g_vth);
    cudaGetSymbolAddress((void**)&wqt, g_wq);
    cudaGetSymbolAddress((void**)&wkt, g_wk);
    cudaGetSymbolAddress((void**)&wvt, g_wv);
    cudaGetSymbolAddress((void**)&wot, g_wo);

    cudaFuncSetAttribute(gemm_qkv, cudaFuncAttributeMaxDynamicSharedMemorySize, G_SMEM);
    cudaFuncSetAttribute(gemm_f16x2, cudaFuncAttributeMaxDynamicSharedMemorySize, G_SMEM);
    cudaFuncSetAttribute(flash_hmma, cudaFuncAttributeMaxDynamicSharedMemorySize, F_SMEM);

    // 1) input prep: hs fp16 split + weight transposes (one launch)
    prep_inputs<<<18432, 256>>>(hs, wq, wk, wv, wo, hsh, hsl,
                                wqt, wkt, wvt, wot);
    // 2) fused QKV projection (fp16x2)
    gemm_qkv<<<dim3(48, S_LEN / 128), 256, G_SMEM>>>(
        hsh, hsl, wqt, wkt, wvt, qp, kp, vp);
    // 3) attention prep: rms+rope Q/K -> fp16, V -> transposed fp16
    prep_attn<<<12288, 256>>>(qp, kp, vp, cosp, sinp, qnw, knw, qh, kh, vth);
    // 4) causal flash attention (fp16, 1-pass S + 1-pass PV)
    flash_hmma<<<dim3(S_LEN / FBM, HQ), 128, F_SMEM>>>(qh, kh, vth, ath, atl);
    // 5) output projection (fp16x2)
    gemm_f16x2<<<dim3(HIDDEN / 64, S_LEN / 128), 256, G_SMEM>>>(
        ath, atl, wot, out, S_LEN, HIDDEN, QSTR);
}

// round 13
// speedup vs baseline: 2.3590x; 1.3349x over previous
#include <cuda_runtime.h>
#include <cuda_fp16.h>
#include <math.h>
#include <stdint.h>

#define S_LEN 4096
#define HIDDEN 2048
#define HQ 16
#define HKV 4
#define DHD 128
#define QSTR (HQ*DHD)    // 2048
#define KSTR (HKV*DHD)   // 512
#define RMS_EPS 1e-6f
#define SM_SCALE 0.08838834764831845f  // 128^-0.5

// ------------------------- scratch (static device globals) ----------------------
__device__ float g_q[S_LEN * QSTR];
__device__ float g_k[S_LEN * KSTR];
__device__ float g_v[S_LEN * KSTR];

// fp16 activations (single precision level now)
__device__ __half g_hs[S_LEN * HIDDEN];
__device__ __half g_at[S_LEN * QSTR];
// flash operands: single fp16 (q, k, v^T)
__device__ __half g_qh[S_LEN * QSTR];
__device__ __half g_kh[S_LEN * KSTR];
__device__ __half g_vth[KSTR * S_LEN];   // [hk*128+d][s]
// transposed weights [N, K] single fp16
__device__ __half g_wq[QSTR * HIDDEN];
__device__ __half g_wk[KSTR * HIDDEN];
__device__ __half g_wv[KSTR * HIDDEN];
__device__ __half g_wo[HIDDEN * QSTR];

// ------------------------- helpers ----------------------------------------------
__device__ __forceinline__ uint32_t smem_u32(const void* p) {
    uint32_t a;
    asm("{ .reg .u64 t; cvta.to.shared.u64 t, %1; cvt.u32.u64 %0, t; }" : "=r"(a) : "l"(p));
    return a;
}
__device__ __forceinline__ void ldsm_x4(uint32_t* r, uint32_t addr) {
    asm volatile("ldmatrix.sync.aligned.m8n8.x4.shared.b16 {%0,%1,%2,%3}, [%4];"
                 : "=r"(r[0]), "=r"(r[1]), "=r"(r[2]), "=r"(r[3]) : "r"(addr));
}
__device__ __forceinline__ void mma_f16(float* d, const uint32_t* a, const uint32_t* b,
                                        const float* c) {
    asm volatile(
        "mma.sync.aligned.m16n8k16.row.col.f32.f16.f16.f32 "
        "{%0,%1,%2,%3}, {%4,%5,%6,%7}, {%8,%9}, {%10,%11,%12,%13};"
        : "=f"(d[0]), "=f"(d[1]), "=f"(d[2]), "=f"(d[3])
        : "r"(a[0]), "r"(a[1]), "r"(a[2]), "r"(a[3]),
          "r"(b[0]), "r"(b[1]),
          "f"(c[0]), "f"(c[1]), "f"(c[2]), "f"(c[3]));
}
__device__ __forceinline__ void cp_async16(uint32_t dst, const void* src) {
    asm volatile("cp.async.cg.shared.global [%0], [%1], 16;" :: "r"(dst), "l"(src) : "memory");
}
__device__ __forceinline__ void cp_commit() {
    asm volatile("cp.async.commit_group;" ::: "memory");
}
template<int N> __device__ __forceinline__ void cp_wait() {
    asm volatile("cp.async.wait_group %0;" :: "n"(N) : "memory");
}
// logical tile rows of 64B (32 fp16) with XOR swizzle
__device__ __forceinline__ uint32_t swz(uint32_t tileBase, int r, int c) {
    uint32_t off = r * 64 + c * 16;
    off ^= ((off >> 7) & 7) << 4;
    return tileBase + off;
}

// ------------------------- transpose device core (fp16 single) -------------------
__device__ __forceinline__ void wt_tile_h(
    const float* __restrict__ W, __half* __restrict__ Th,
    int K, int N, int n0, int k0)
{
    __shared__ float t[32][33];
    int tx = threadIdx.x & 31, ty = threadIdx.x >> 5;
#pragma unroll
    for (int j = 0; j < 4; j++)
        t[ty + 8 * j][tx] = W[(size_t)(k0 + ty + 8 * j) * N + n0 + tx];
    __syncthreads();
#pragma unroll
    for (int j = 0; j < 4; j++) {
        size_t o = (size_t)(n0 + ty + 8 * j) * K + k0 + tx;
        Th[o] = __float2half(t[tx][ty + 8 * j]);
    }
}

// merged input prep: hs fp16 convert (8192 blocks) + 4 weight transposes (10240)
__global__ __launch_bounds__(256) void prep_inputs(
    const float* __restrict__ hs,
    const float* __restrict__ wq, const float* __restrict__ wk,
    const float* __restrict__ wv, const float* __restrict__ wo,
    __half* __restrict__ hsh,
    __half* __restrict__ wqt, __half* __restrict__ wkt,
    __half* __restrict__ wvt, __half* __restrict__ wot)
{
    int b = blockIdx.x;
    if (b < 8192) {
        int i = (b * 256 + threadIdx.x) * 4;
        float4 v = *(const float4*)(hs + i);
        *(__half2*)(hsh + i)     = __floats2half2_rn(v.x, v.y);
        *(__half2*)(hsh + i + 2) = __floats2half2_rn(v.z, v.w);
        return;
    }
    b -= 8192;
    if (b < 4096)
        wt_tile_h(wq, wqt, HIDDEN, QSTR, (b & 63) * 32, (b >> 6) * 32);
    else if (b < 5120) {
        int l = b - 4096;
        wt_tile_h(wk, wkt, HIDDEN, KSTR, (l & 15) * 32, (l >> 4) * 32);
    } else if (b < 6144) {
        int l = b - 5120;
        wt_tile_h(wv, wvt, HIDDEN, KSTR, (l & 15) * 32, (l >> 4) * 32);
    } else {
        int l = b - 6144;
        wt_tile_h(wo, wot, QSTR, HIDDEN, (l & 63) * 32, (l >> 6) * 32);
    }
}

// ------------------------- single-fp16 HMMA GEMM core (K-chunk 64) ---------------
// C = A[M,K] @ B[N,K]^T, both single fp16 (1 pass).
// CTA 128x64, warp tile 32x32, 8 warps, double-buffered. 48 KB smem.
#define GA_SUB 8192                    // 128x32 fp16 subtile
#define GB_SUB 4096                    // 64x32 fp16 subtile
#define GSTAGE (2 * GA_SUB + 2 * GB_SUB)   // 24576
#define G_SMEM (2 * GSTAGE)                // 49152

__device__ __forceinline__ void gemm_stage(
    uint32_t st, int k0, int tid, int K,
    const __half* __restrict__ A0, const __half* __restrict__ B0)
{
#pragma unroll
    for (int s2 = 0; s2 < 6; s2++) {
        int i = tid + 256 * s2;
        if (i < 1024) {
            int idx = i >> 9;               // 0..1 : A sub 0/1
            int r = (i >> 2) & 127, x = i & 3;
            cp_async16(swz(st + idx * GA_SUB, r, x),
                       A0 + (size_t)r * K + k0 + idx * 32 + x * 8);
        } else {
            int j = i - 1024;               // 0..511
            int idx = j >> 8;               // 0..1 : B sub 0/1
            int r = (j >> 2) & 63, x = j & 3;
            cp_async16(swz(st + 2 * GA_SUB + idx * GB_SUB, r, x),
                       B0 + (size_t)r * K + k0 + idx * 32 + x * 8);
        }
    }
    cp_commit();
}

__device__ __forceinline__ void gemm_core(
    const __half* __restrict__ A0, const __half* __restrict__ B0,
    float* __restrict__ C0, int ldc, int K, uint32_t sb)
{
    const int tid  = threadIdx.x;
    const int wid  = tid >> 5;
    const int lane = tid & 31;
    const int mBase = (wid >> 1) * 32;
    const int nBase = (wid & 1) * 32;
    const int lr = lane & 15, lc = lane >> 4;

    float acc[2][4][4];
#pragma unroll
    for (int f = 0; f < 2; f++)
#pragma unroll
        for (int j = 0; j < 4; j++)
#pragma unroll
            for (int x = 0; x < 4; x++) acc[f][j][x] = 0.f;

    const int nChunks = K >> 6;
    gemm_stage(sb, 0, tid, K, A0, B0);

    for (int kc = 0; kc < nChunks; kc++) {
        const uint32_t st = sb + (kc & 1) * GSTAGE;
        if (kc + 1 < nChunks) {
            gemm_stage(sb + ((kc + 1) & 1) * GSTAGE, (kc + 1) << 6, tid, K, A0, B0);
            cp_wait<1>();
        } else {
            cp_wait<0>();
        }
        __syncthreads();

#pragma unroll
        for (int s16 = 0; s16 < 4; s16++) {
            const int sub = s16 >> 1;
            const int ch  = (s16 & 1) * 2 + lc;
            const uint32_t tA = st + sub * GA_SUB;
            const uint32_t tB = st + 2 * GA_SUB + sub * GB_SUB;

            uint32_t ah[2][4], bb[2][4];
#pragma unroll
            for (int f = 0; f < 2; f++)
                ldsm_x4(ah[f], swz(tA, mBase + f * 16 + lr, ch));
#pragma unroll
            for (int g = 0; g < 2; g++)
                ldsm_x4(bb[g], swz(tB, nBase + g * 16 + lr, ch));
#pragma unroll
            for (int f = 0; f < 2; f++)
#pragma unroll
                for (int j = 0; j < 4; j++) {
                    uint32_t bfr[2] = {bb[j >> 1][j & 1], bb[j >> 1][2 + (j & 1)]};
                    mma_f16(acc[f][j], ah[f], bfr, acc[f][j]);
                }
        }
        __syncthreads();
    }

    const int erow = lane >> 2;
    const int ecol = (lane & 3) * 2;
#pragma unroll
    for (int f = 0; f < 2; f++) {
        int rl = mBase + f * 16 + erow;
#pragma unroll
        for (int j = 0; j < 4; j++) {
            int cl = nBase + j * 8 + ecol;
            *(float2*)(C0 + (size_t)rl * ldc + cl)       = make_float2(acc[f][j][0], acc[f][j][1]);
            *(float2*)(C0 + (size_t)(rl + 8) * ldc + cl) = make_float2(acc[f][j][2], acc[f][j][3]);
        }
    }
}

__global__ __launch_bounds__(256, 2) void gemm_qkv(
    const __half* __restrict__ A,
    const __half* __restrict__ wqt, const __half* __restrict__ wkt,
    const __half* __restrict__ wvt,
    float* __restrict__ Q, float* __restrict__ K, float* __restrict__ V)
{
    extern __shared__ char smc[];
    const uint32_t sb = smem_u32(smc);
    const int bx = blockIdx.x;
    const int m0 = blockIdx.y * 128;

    const __half* B;
    float* C;
    int n0, ldc;
    if (bx < 32)      { B = wqt; C = Q; n0 = bx * 64;        ldc = QSTR; }
    else if (bx < 40) { B = wkt; C = K; n0 = (bx - 32) * 64; ldc = KSTR; }
    else              { B = wvt; C = V; n0 = (bx - 40) * 64; ldc = KSTR; }

    gemm_core(A + (size_t)m0 * HIDDEN, B + (size_t)n0 * HIDDEN,
              C + (size_t)m0 * ldc + n0, ldc, HIDDEN, sb);
}

__global__ __launch_bounds__(256, 2) void gemm_f16(
    const __half* __restrict__ A, const __half* __restrict__ B,
    float* __restrict__ C, int M, int N, int K)
{
    extern __shared__ char smc[];
    const uint32_t sb = smem_u32(smc);
    const int m0 = blockIdx.y * 128, n0 = blockIdx.x * 64;
    gemm_core(A + (size_t)m0 * K, B + (size_t)n0 * K,
              C + (size_t)m0 * N + n0, N, K, sb);
}

// ------------------------- fused attention prep (one launch) ---------------------
__device__ __forceinline__ void rms_rope_rows_h(
    const float* __restrict__ in, const float* __restrict__ cosp,
    const float* __restrict__ sinp, const float* __restrict__ w,
    int nh, float outScale, int rowBase, __half* __restrict__ H)
{
    const int lane = threadIdx.x & 31;
    const int rowIdx = rowBase + (threadIdx.x >> 5);
    const int s = rowIdx / nh;
    const int d0 = lane * 2;

    const float* x = in + (size_t)rowIdx * DHD;
    float2 a = *(const float2*)(x + d0);
    float2 b = *(const float2*)(x + 64 + d0);

    float ss = a.x * a.x + a.y * a.y + b.x * b.x + b.y * b.y;
#pragma unroll
    for (int o = 16; o > 0; o >>= 1) ss += __shfl_xor_sync(0xFFFFFFFFu, ss, o);
    float inv = rsqrtf(ss * (1.0f / DHD) + RMS_EPS);

    float2 wa = *(const float2*)(w + d0);
    float2 wb = *(const float2*)(w + 64 + d0);
    const float* cs = cosp + (size_t)s * DHD;
    const float* sn = sinp + (size_t)s * DHD;
    float2 ca = *(const float2*)(cs + d0), cb = *(const float2*)(cs + 64 + d0);
    float2 sa = *(const float2*)(sn + d0), sb2 = *(const float2*)(sn + 64 + d0);

    float xa0 = a.x * inv * wa.x, xa1 = a.y * inv * wa.y;
    float xb0 = b.x * inv * wb.x, xb1 = b.y * inv * wb.y;
    float oa0 = (xa0 * ca.x - xb0 * sa.x) * outScale;
    float oa1 = (xa1 * ca.y - xb1 * sa.y) * outScale;
    float ob0 = (xb0 * cb.x + xa0 * sb2.x) * outScale;
    float ob1 = (xb1 * cb.y + xa1 * sb2.y) * outScale;

    size_t off = (size_t)rowIdx * DHD + d0;
    *(__half2*)(H + off)      = __floats2half2_rn(oa0, oa1);
    *(__half2*)(H + off + 64) = __floats2half2_rn(ob0, ob1);
}

__global__ __launch_bounds__(256) void prep_attn(
    const float* __restrict__ qp, const float* __restrict__ kp,
    const float* __restrict__ vp,
    const float* __restrict__ cosp, const float* __restrict__ sinp,
    const float* __restrict__ qnw, const float* __restrict__ knw,
    __half* __restrict__ qh, __half* __restrict__ kh,
    __half* __restrict__ vth)
{
    int b = blockIdx.x;
    if (b < 8192)
        rms_rope_rows_h(qp, cosp, sinp, qnw, HQ, SM_SCALE, b * 8, qh);
    else if (b < 10240)
        rms_rope_rows_h(kp, cosp, sinp, knw, HKV, 1.0f, (b - 8192) * 8, kh);
    else {
        int l = b - 10240;
        wt_tile_h(vp, vth, S_LEN, KSTR, (l & 15) * 32, (l >> 4) * 32);
    }
}

// ------------------------- fp16 HMMA causal flash attention ----------------------
// 1-pass S (fp16 q,k), 1-pass PV (fp16 p,v). Double-buffered K/V slots.
#define FBM 64
#define FBN 64
#define FQ_OFF 0
#define FK_OFF(i) (16384 + (i) * 16384)
#define FV_OFF(i) (49152 + (i) * 16384)
#define F_SMEM 81920

__device__ __forceinline__ void flash_load_k(
    uint32_t dst, int tid, int kg0, int hk, const __half* Kh)
{
#pragma unroll
    for (int s = 0; s < 8; s++) {
        int i = tid + 128 * s;
        int c = i >> 8, r = (i >> 2) & 63, x = i & 3;
        cp_async16(swz(dst + c * 4096, r, x),
                   Kh + ((size_t)(kg0 + r) * HKV + hk) * DHD + c * 32 + x * 8);
    }
}
__device__ __forceinline__ void flash_load_v(
    uint32_t dst, int tid, int kg0, int hk, const __half* Vth)
{
#pragma unroll
    for (int s = 0; s < 8; s++) {
        int i = tid + 128 * s;
        int kc = i >> 9, r = (i >> 2) & 127, x = i & 3;
        cp_async16(swz(dst + kc * 8192, r, x),
                   Vth + (size_t)(hk * DHD + r) * S_LEN + kg0 + kc * 32 + x * 8);
    }
}

__global__ __launch_bounds__(128, 2) void flash_hmma(
    const __half* __restrict__ Qh, const __half* __restrict__ Kh,
    const __half* __restrict__ Vth,
    __half* __restrict__ O)
{
    extern __shared__ char smf[];
    const uint32_t sb = smem_u32(smf);
    const int tid = threadIdx.x, wid = tid >> 5, lane = tid & 31;
    const int qt = (int)gridDim.x - 1 - (int)blockIdx.x;   // heavy tiles first
    const int h = blockIdx.y, hk = h >> 2;
    const int qm0 = qt * FBM;
    const int wBase = wid * 16;
    const int lr = lane & 15, lc = lane >> 4;
    const int erow = lane >> 2, q4 = lane & 3;

#pragma unroll
    for (int s = 0; s < 8; s++) {
        int i = tid + 128 * s;
        int c = i >> 8, r = (i >> 2) & 63, x = i & 3;
        cp_async16(swz(sb + FQ_OFF + c * 4096, r, x),
                   Qh + ((size_t)(qm0 + r) * HQ + h) * DHD + c * 32 + x * 8);
    }
    flash_load_k(sb + FK_OFF(0), tid, 0, hk, Kh);
    cp_commit();
    flash_load_v(sb + FV_OFF(0), tid, 0, hk, Vth);
    cp_commit();

    uint32_t qf[8][4];
    float oacc[16][4];
#pragma unroll
    for (int jj = 0; jj < 16; jj++)
#pragma unroll
        for (int x = 0; x < 4; x++) oacc[jj][x] = 0.f;
    float m0 = -1e30f, m1 = -1e30f, l0 = 0.f, l1 = 0.f;

    for (int t = 0; t <= qt; t++) {
        const uint32_t kb = sb + FK_OFF(t & 1);
        const uint32_t vb = sb + FV_OFF(t & 1);

        cp_wait<1>();
        __syncthreads();

        if (t == 0) {
#pragma unroll
            for (int kk = 0; kk < 8; kk++) {
                int c = kk >> 1, x = (kk & 1) * 2 + lc;
                ldsm_x4(qf[kk], swz(sb + FQ_OFF + c * 4096, wBase + lr, x));
            }
        }

        if (t < qt) {
            flash_load_k(sb + FK_OFF((t + 1) & 1), tid, (t + 1) * FBN, hk, Kh);
            cp_commit();
        }

        float sacc[8][4];
#pragma unroll
        for (int j = 0; j < 8; j++)
#pragma unroll
            for (int x = 0; x < 4; x++) sacc[j][x] = 0.f;

#pragma unroll
        for (int kk = 0; kk < 8; kk++) {
            int c = kk >> 1, x = (kk & 1) * 2 + lc;
            uint32_t kbf[4][4];
#pragma unroll
            for (int g = 0; g < 4; g++)
                ldsm_x4(kbf[g], swz(kb + c * 4096, g * 16 + lr, x));
#pragma unroll
            for (int j = 0; j < 8; j++) {
                uint32_t bf[2] = {kbf[j >> 1][j & 1], kbf[j >> 1][(j & 1) + 2]};
                mma_f16(sacc[j], qf[kk], bf, sacc[j]);
            }
        }

        if (t == qt) {
            int row0 = qm0 + wBase + erow, row1 = row0 + 8;
            int colb = t * FBN + q4 * 2;
#pragma unroll
            for (int j = 0; j < 8; j++) {
                int c0 = colb + j * 8, c1 = c0 + 1;
                if (c0 > row0) sacc[j][0] = -1e30f;
                if (c1 > row0) sacc[j][1] = -1e30f;
                if (c0 > row1) sacc[j][2] = -1e30f;
                if (c1 > row1) sacc[j][3] = -1e30f;
            }
        }

        float mx0 = -1e30f, mx1 = -1e30f;
#pragma unroll
        for (int j = 0; j < 8; j++) {
            mx0 = fmaxf(mx0, fmaxf(sacc[j][0], sacc[j][1]));
            mx1 = fmaxf(mx1, fmaxf(sacc[j][2], sacc[j][3]));
        }
        mx0 = fmaxf(mx0, __shfl_xor_sync(0xFFFFFFFFu, mx0, 1));
        mx0 = fmaxf(mx0, __shfl_xor_sync(0xFFFFFFFFu, mx0, 2));
        mx1 = fmaxf(mx1, __shfl_xor_sync(0xFFFFFFFFu, mx1, 1));
        mx1 = fmaxf(mx1, __shfl_xor_sync(0xFFFFFFFFu, mx1, 2));
        float mn0 = fmaxf(m0, mx0), mn1 = fmaxf(m1, mx1);
        float a0 = __expf(m0 - mn0), a1 = __expf(m1 - mn1);
        float s0 = 0.f, s1 = 0.f;
#pragma unroll
        for (int j = 0; j < 8; j++) {
            float p0 = __expf(sacc[j][0] - mn0); sacc[j][0] = p0; s0 += p0;
            float p1 = __expf(sacc[j][1] - mn0); sacc[j][1] = p1; s0 += p1;
            float p2 = __expf(sacc[j][2] - mn1); sacc[j][2] = p2; s1 += p2;
            float p3 = __expf(sacc[j][3] - mn1); sacc[j][3] = p3; s1 += p3;
        }
        s0 += __shfl_xor_sync(0xFFFFFFFFu, s0, 1);
        s0 += __shfl_xor_sync(0xFFFFFFFFu, s0, 2);
        s1 += __shfl_xor_sync(0xFFFFFFFFu, s1, 1);
        s1 += __shfl_xor_sync(0xFFFFFFFFu, s1, 2);
        l0 = l0 * a0 + s0;
        l1 = l1 * a1 + s1;
        m0 = mn0; m1 = mn1;
#pragma unroll
        for (int jj = 0; jj < 16; jj++) {
            oacc[jj][0] *= a0; oacc[jj][1] *= a0;
            oacc[jj][2] *= a1; oacc[jj][3] *= a1;
        }

        if (t < qt) cp_wait<1>(); else cp_wait<0>();
        __syncthreads();

        if (t < qt) {
            flash_load_v(sb + FV_OFF((t + 1) & 1), tid, (t + 1) * FBN, hk, Vth);
            cp_commit();
        }

        // O += P @ V  (single fp16 P)
#pragma unroll
        for (int tt = 0; tt < 4; tt++) {
            uint32_t ph[4];
            {
                __half2 v0 = __floats2half2_rn(sacc[2*tt][0],   sacc[2*tt][1]);
                __half2 v1 = __floats2half2_rn(sacc[2*tt][2],   sacc[2*tt][3]);
                __half2 v2 = __floats2half2_rn(sacc[2*tt+1][0], sacc[2*tt+1][1]);
                __half2 v3 = __floats2half2_rn(sacc[2*tt+1][2], sacc[2*tt+1][3]);
                ph[0] = *(uint32_t*)&v0; ph[1] = *(uint32_t*)&v1;
                ph[2] = *(uint32_t*)&v2; ph[3] = *(uint32_t*)&v3;
            }
            int kc = tt >> 1, x = (tt & 1) * 2 + lc;
            uint32_t vbf[8][4];
#pragma unroll
            for (int g = 0; g < 8; g++)
                ldsm_x4(vbf[g], swz(vb + kc * 8192, g * 16 + lr, x));
#pragma unroll
            for (int jj = 0; jj < 16; jj++) {
                uint32_t bf[2] = {vbf[jj >> 1][jj & 1], vbf[jj >> 1][(jj & 1) + 2]};
                mma_f16(oacc[jj], ph, bf, oacc[jj]);
            }
        }
    }

    // epilogue: divide by l, write single fp16
    float il0 = 1.0f / l0, il1 = 1.0f / l1;
    int row0 = qm0 + wBase + erow;
#pragma unroll
    for (int jj = 0; jj < 16; jj++) {
        int col = jj * 8 + q4 * 2;
        *(__half2*)(O + (size_t)row0 * QSTR + h * DHD + col) =
            __floats2half2_rn(oacc[jj][0] * il0, oacc[jj][1] * il0);
        *(__half2*)(O + (size_t)(row0 + 8) * QSTR + h * DHD + col) =
            __floats2half2_rn(oacc[jj][2] * il1, oacc[jj][3] * il1);
    }
}

// ------------------------- launch -----------------------------------------------
extern "C" void kernel_launch(void* const* d_in, const int* in_sizes, int n_in,
                              void* d_out, int out_size)
{
    (void)in_sizes; (void)n_in; (void)out_size;
    const float* hs   = (const float*)d_in[0];
    const float* cosp = (const float*)d_in[1];
    const float* sinp = (const float*)d_in[2];
    const float* wq   = (const float*)d_in[3];
    const float* wk   = (const float*)d_in[4];
    const float* wv   = (const float*)d_in[5];
    const float* wo   = (const float*)d_in[6];
    const float* qnw  = (const float*)d_in[7];
    const float* knw  = (const float*)d_in[8];
    float* out = (float*)d_out;

    float *qp, *kp, *vp;
    cudaGetSymbolAddress((void**)&qp, g_q);
    cudaGetSymbolAddress((void**)&kp, g_k);
    cudaGetSymbolAddress((void**)&vp, g_v);
    __half *hsh, *ath, *qh, *kh, *vth;
    __half *wqt, *wkt, *wvt, *wot;
    cudaGetSymbolAddress((void**)&hsh, g_hs);
    cudaGetSymbolAddress((void**)&ath, g_at);
    cudaGetSymbolAddress((void**)&qh, g_qh);
    cudaGetSymbolAddress((void**)&kh, g_kh);
    cudaGetSymbolAddress((void**)&vth, g_vth);
    cudaGetSymbolAddress((void**)&wqt, g_wq);
    cudaGetSymbolAddress((void**)&wkt, g_wk);
    cudaGetSymbolAddress((void**)&wvt, g_wv);
    cudaGetSymbolAddress((void**)&wot, g_wo);

    cudaFuncSetAttribute(gemm_qkv, cudaFuncAttributeMaxDynamicSharedMemorySize, G_SMEM);
    cudaFuncSetAttribute(gemm_f16, cudaFuncAttributeMaxDynamicSharedMemorySize, G_SMEM);
    cudaFuncSetAttribute(flash_hmma, cudaFuncAttributeMaxDynamicSharedMemorySize, F_SMEM);

    // 1) input prep: hs -> fp16, weight transposes (one launch)
    prep_inputs<<<18432, 256>>>(hs, wq, wk, wv, wo, hsh,
                                wqt, wkt, wvt, wot);
    // 2) fused QKV projection (single fp16)
    gemm_qkv<<<dim3(48, S_LEN / 128), 256, G_SMEM>>>(
        hsh, wqt, wkt, wvt, qp, kp, vp);
    // 3) attention prep: rms+rope Q/K -> fp16, V -> transposed fp16
    prep_attn<<<12288, 256>>>(qp, kp, vp, cosp, sinp, qnw, knw, qh, kh, vth);
    // 4) causal flash attention (fp16, 1-pass S + 1-pass PV)
    flash_hmma<<<dim3(S_LEN / FBM, HQ), 128, F_SMEM>>>(qh, kh, vth, ath);
    // 5) output projection (single fp16)
    gemm_f16<<<dim3(HIDDEN / 64, S_LEN / 128), 256, G_SMEM>>>(
        ath, wot, out, S_LEN, HIDDEN, QSTR);
}